// round 1
// baseline (speedup 1.0000x reference)
#include <cuda_runtime.h>
#include <math.h>
#include <stdint.h>

#define VOCAB 32000
#define HID   1024
#define BEAM  16
#define TSTEPS 16

// ---------------- device scratch (static, allocation-free) ----------------
__device__ float g_z[BEAM * VOCAB];      // raw logits per beam
__device__ float g_off[BEAM];            // logsumexp offset per beam row
__device__ float g_tv[BEAM * BEAM];      // per-row top-16 values (logprob domain)
__device__ int   g_ti[BEAM * BEAM];      // per-row top-16 indices
__device__ int   g_seq[TSTEPS * BEAM];   // beam_seq [t][b]
__device__ float g_seqlp[TSTEPS * BEAM]; // beam_seq_lp [t][b]
__device__ float g_lps[BEAM];            // beam_lps
__device__ int   g_tok[BEAM];            // selected token per beam this step
__device__ int   g_perm[BEAM];           // selected source beam per beam
__device__ float g_x[2 * HID * BEAM];    // gathered [embed_row ; state_row] as [k][b]
__device__ float g_st[HID * BEAM];       // hidden state, col-major [k][b]
__device__ float g_acc[HID * BEAM];      // rnn partial accumulator [k][b]

// ---------------- small helpers ----------------
__device__ __forceinline__ unsigned long long pack_key(float v, unsigned idx_inv) {
    unsigned u = __float_as_uint(v);
    u = (u & 0x80000000u) ? ~u : (u | 0x80000000u);
    return ((unsigned long long)u << 32) | (unsigned long long)idx_inv;
}
__device__ __forceinline__ float unpack_val(unsigned long long k) {
    unsigned u = (unsigned)(k >> 32);
    u = (u & 0x80000000u) ? (u ^ 0x80000000u) : ~u;
    return __uint_as_float(u);
}
__device__ __forceinline__ unsigned long long pack2f(float lo, float hi) {
    unsigned long long r;
    asm("mov.b64 %0, {%1, %2};" : "=l"(r) : "r"(__float_as_uint(lo)), "r"(__float_as_uint(hi)));
    return r;
}
__device__ __forceinline__ void unpack2(unsigned long long a, float& lo, float& hi) {
    unsigned ulo, uhi;
    asm("mov.b64 {%0, %1}, %2;" : "=r"(ulo), "=r"(uhi) : "l"(a));
    lo = __uint_as_float(ulo); hi = __uint_as_float(uhi);
}
__device__ __forceinline__ unsigned long long fma2(unsigned long long a, unsigned long long b,
                                                   unsigned long long c) {
    unsigned long long d;
    asm("fma.rn.f32x2 %0, %1, %2, %3;" : "=l"(d) : "l"(a), "l"(b), "l"(c));
    return d;
}

// block-wide reductions for blockDim.x == 256 (8 warps)
__device__ __forceinline__ float blockMaxF(float v) {
    __shared__ float red[8]; __shared__ float out;
    #pragma unroll
    for (int o = 16; o; o >>= 1) v = fmaxf(v, __shfl_down_sync(0xffffffffu, v, o));
    if ((threadIdx.x & 31) == 0) red[threadIdx.x >> 5] = v;
    __syncthreads();
    if (threadIdx.x < 32) {
        float w = (threadIdx.x < 8) ? red[threadIdx.x] : -INFINITY;
        #pragma unroll
        for (int o = 4; o; o >>= 1) w = fmaxf(w, __shfl_down_sync(0xffffffffu, w, o));
        if (threadIdx.x == 0) out = w;
    }
    __syncthreads();
    float r = out; __syncthreads();
    return r;
}
__device__ __forceinline__ float blockSumF(float v) {
    __shared__ float red[8]; __shared__ float out;
    #pragma unroll
    for (int o = 16; o; o >>= 1) v += __shfl_down_sync(0xffffffffu, v, o);
    if ((threadIdx.x & 31) == 0) red[threadIdx.x >> 5] = v;
    __syncthreads();
    if (threadIdx.x < 32) {
        float w = (threadIdx.x < 8) ? red[threadIdx.x] : 0.0f;
        #pragma unroll
        for (int o = 4; o; o >>= 1) w += __shfl_down_sync(0xffffffffu, w, o);
        if (threadIdx.x == 0) out = w;
    }
    __syncthreads();
    float r = out; __syncthreads();
    return r;
}
__device__ __forceinline__ unsigned long long blockMaxU64(unsigned long long v) {
    __shared__ unsigned long long red[8]; __shared__ unsigned long long out;
    #pragma unroll
    for (int o = 16; o; o >>= 1) {
        unsigned long long w = __shfl_down_sync(0xffffffffu, v, o);
        if (w > v) v = w;
    }
    if ((threadIdx.x & 31) == 0) red[threadIdx.x >> 5] = v;
    __syncthreads();
    if (threadIdx.x < 32) {
        unsigned long long w = (threadIdx.x < 8) ? red[threadIdx.x] : 0ull;
        #pragma unroll
        for (int o = 4; o; o >>= 1) {
            unsigned long long t = __shfl_down_sync(0xffffffffu, w, o);
            if (t > w) w = t;
        }
        if (threadIdx.x == 0) out = w;
    }
    __syncthreads();
    unsigned long long r = out; __syncthreads();
    return r;
}

// ---------------- kernels ----------------

// initialize state / beam arrays
__global__ void k_init(const float* __restrict__ state) {
    int i = blockIdx.x * 256 + threadIdx.x;
    if (i < HID * BEAM) {
        int k = i >> 4, b = i & 15;
        g_st[i] = state[b * HID + k];
    }
    if (i < TSTEPS * BEAM) { g_seq[i] = 0; g_seqlp[i] = 0.0f; }
    if (i < BEAM) g_lps[i] = 0.0f;
}

// Per-beam-row: compute off = logsumexp(z_row), then exact top-16 of
// lpf = z - off (with -1000 on last vocab entry), jax top_k tie-breaking.
__global__ void k_stats_topk(const float* __restrict__ ext, int use_ext) {
    int row = blockIdx.x, tid = threadIdx.x;
    const float* __restrict__ src = use_ext ? (ext + (size_t)row * VOCAB)
                                            : (g_z + (size_t)row * VOCAB);
    // pass 1: row max
    float m = -INFINITY;
    for (int c = tid; c < VOCAB; c += 256) m = fmaxf(m, src[c]);
    m = blockMaxF(m);
    // pass 2: sum exp
    float s = 0.0f;
    for (int c = tid; c < VOCAB; c += 256) s += expf(src[c] - m);
    s = blockSumF(s);
    float off = m + logf(s);
    if (tid == 0) g_off[row] = off;

    // pass 3: per-thread local top-16 (sorted desc) in smem, then 16 rounds
    __shared__ unsigned long long cand[16 * 256];
    #pragma unroll
    for (int j = 0; j < 16; j++) cand[j * 256 + tid] = 0ull;
    unsigned long long s15 = 0ull;
    for (int c = tid; c < VOCAB; c += 256) {
        float v = src[c] - off;
        if (c == VOCAB - 1) v -= 1000.0f;
        unsigned long long key = pack_key(v, 0xFFFFFFFFu - (unsigned)c);
        if (key > s15) {
            int j = 15;
            while (j > 0 && cand[(j - 1) * 256 + tid] < key) {
                cand[j * 256 + tid] = cand[(j - 1) * 256 + tid];
                j--;
            }
            cand[j * 256 + tid] = key;
            s15 = cand[15 * 256 + tid];
        }
    }
    __syncthreads();
    // 16 rounds of "max among keys strictly below previous winner"
    unsigned long long prev = ~0ull;
    int p = 0;
    for (int r = 0; r < 16; r++) {
        while (p < 16 && cand[p * 256 + tid] >= prev) p++;
        unsigned long long h = (p < 16) ? cand[p * 256 + tid] : 0ull;
        unsigned long long win = blockMaxU64(h);
        if (tid == 0) {
            unsigned lo = (unsigned)win;
            g_ti[row * 16 + r] = (int)(0xFFFFFFFFu - lo);
            g_tv[row * 16 + r] = unpack_val(win);
        }
        prev = win;
    }
}

// second-level selection over 16x16 candidates; updates beam arrays
__global__ void k_select(int t) {
    int tid = threadIdx.x;
    int q = tid >> 4;
    float tvv = g_tv[tid];
    float cv = g_lps[q] + tvv;
    if (t == 0 && q != 0) cv = -INFINITY;
    unsigned long long key = pack_key(cv, 0xFFFFFFFFu - (unsigned)tid);

    __shared__ int   s_q[16], s_c[16];
    __shared__ float s_r[16], s_nl[16];

    unsigned long long prev = ~0ull;
    for (int r = 0; r < 16; r++) {
        unsigned long long h = (key < prev) ? key : 0ull;
        unsigned long long win = blockMaxU64(h);
        if (h == win && h != 0ull) {
            int c = g_ti[tid];
            s_q[r] = q; s_c[r] = c; s_r[r] = tvv;
            s_nl[r] = (c == 0 || t == TSTEPS - 1) ? -1000.0f : cv;
        }
        prev = win;
    }
    __syncthreads();

    __shared__ int   oseq[256];
    __shared__ float oslp[256];
    oseq[tid] = g_seq[tid];
    oslp[tid] = g_seqlp[tid];
    __syncthreads();

    int row = tid >> 4, j = tid & 15;
    if (row < t) {
        g_seq[tid]   = oseq[row * 16 + s_q[j]];
        g_seqlp[tid] = oslp[row * 16 + s_q[j]];
    } else if (row == t) {
        g_seq[tid]   = s_c[j];
        g_seqlp[tid] = s_r[j];
    }
    if (tid < 16) {
        g_lps[tid]  = s_nl[tid];
        g_tok[tid]  = s_c[tid];
        g_perm[tid] = s_q[tid];
    }
}

// gather x = [embed[tok[b]] ; st_old[perm[b]]] into [k][b] layout; zero g_acc
__global__ void k_gather(const float* __restrict__ embed) {
    int i = blockIdx.x * 256 + threadIdx.x;   // 192*256 = 49152
    if (i < 2 * HID * BEAM) {
        int k = i >> 4, b = i & 15;
        g_x[i] = (k < HID) ? embed[(size_t)g_tok[b] * HID + k]
                           : g_st[(k - HID) * 16 + g_perm[b]];
    } else {
        int j = i - 2 * HID * BEAM;
        if (j < HID * BEAM) g_acc[j] = 0.0f;
    }
}

// RNN partial GEMM: g_acc[col][b] += sum_k x[k][b] * W[k][col], K split by blockIdx.y
__global__ void k_rnn(const float* __restrict__ Wih, const float* __restrict__ Whh) {
    int tid = threadIdx.x;
    int col = blockIdx.x * 64 + (tid & 63);
    int bq  = tid >> 6;          // beam quad 0..3
    int ks  = blockIdx.y;        // 0..7, 256 k each (0-3: Wih, 4-7: Whh)
    const float* wp = (ks < 4) ? (Wih + (size_t)(ks * 256) * HID + col)
                               : (Whh + (size_t)(ks * 256 - HID) * HID + col);
    const float* xp = g_x + (size_t)(ks * 256) * 16 + bq * 4;
    unsigned long long a0 = 0ull, a1 = 0ull;
    #pragma unroll 4
    for (int kk = 0; kk < 256; kk++) {
        float w = __ldg(wp); wp += HID;
        unsigned long long ww = pack2f(w, w);
        ulonglong2 xv = *(const ulonglong2*)xp; xp += 16;
        a0 = fma2(xv.x, ww, a0);
        a1 = fma2(xv.y, ww, a1);
    }
    float f0, f1, f2, f3;
    unpack2(a0, f0, f1); unpack2(a1, f2, f3);
    float* dst = g_acc + col * 16 + bq * 4;
    atomicAdd(dst + 0, f0); atomicAdd(dst + 1, f1);
    atomicAdd(dst + 2, f2); atomicAdd(dst + 3, f3);
}

// finish RNN: tanh(acc + b) -> g_st
__global__ void k_rnnfin(const float* __restrict__ bvec) {
    int i = blockIdx.x * 256 + threadIdx.x;
    if (i < HID * BEAM) g_st[i] = tanhf(g_acc[i] + bvec[i >> 4]);
}

// logits: z[beam][col] = sum_k h[beam][k] * W_out[k][col], f32x2 packed FMA
__global__ void k_logits(const float* __restrict__ W) {
    int tid = threadIdx.x;
    int chunk = blockIdx.x, beam = blockIdx.y;
    __shared__ __align__(16) float hx[HID];
    #pragma unroll
    for (int i2 = 0; i2 < 4; i2++) {
        int k = tid + i2 * 256;
        hx[k] = g_st[k * 16 + beam];
    }
    __syncthreads();
    int col = chunk * 2048 + tid * 8;
    if (col >= VOCAB) return;
    const float* wp = W + col;
    unsigned long long a0 = 0ull, a1 = 0ull, a2 = 0ull, a3 = 0ull;
    for (int k = 0; k < HID; k += 4) {
        float4 xv = *(const float4*)(hx + k);
        #pragma unroll
        for (int u = 0; u < 4; u++) {
            float x = (u == 0) ? xv.x : (u == 1) ? xv.y : (u == 2) ? xv.z : xv.w;
            unsigned long long xx = pack2f(x, x);
            ulonglong2 w01 = *(const ulonglong2*)wp;
            ulonglong2 w23 = *(const ulonglong2*)(wp + 4);
            wp += VOCAB;
            a0 = fma2(w01.x, xx, a0); a1 = fma2(w01.y, xx, a1);
            a2 = fma2(w23.x, xx, a2); a3 = fma2(w23.y, xx, a3);
        }
    }
    float r0, r1, r2, r3, r4, r5, r6, r7;
    unpack2(a0, r0, r1); unpack2(a1, r2, r3);
    unpack2(a2, r4, r5); unpack2(a3, r6, r7);
    float* zp = g_z + (size_t)beam * VOCAB + col;
    *(float4*)zp       = make_float4(r0, r1, r2, r3);
    *((float4*)zp + 1) = make_float4(r4, r5, r6, r7);
}

// write outputs: [beam_seq (256 as float) | beam_seq_lp (256) | beam_lps (16)]
__global__ void k_final(float* __restrict__ out) {
    int i = threadIdx.x;
    for (int j = i; j < 528; j += 256) {
        if (j < 256)      out[j] = (float)g_seq[j];
        else if (j < 512) out[j] = g_seqlp[j - 256];
        else              out[j] = g_lps[j - 512];
    }
}

// ---------------- launch ----------------
extern "C" void kernel_launch(void* const* d_in, const int* in_sizes, int n_in,
                              void* d_out, int out_size) {
    const float* state    = (const float*)d_in[0];
    const float* logprobs = (const float*)d_in[1];
    const float* embed    = (const float*)d_in[2];
    const float* W_ih     = (const float*)d_in[3];
    const float* W_hh     = (const float*)d_in[4];
    const float* bvec     = (const float*)d_in[5];
    const float* W_out    = (const float*)d_in[6];
    float* out = (float*)d_out;
    (void)in_sizes; (void)n_in; (void)out_size;

    k_init<<<64, 256>>>(state);
    k_stats_topk<<<16, 256>>>(logprobs, 1);
    for (int t = 0; t < TSTEPS; t++) {
        k_select<<<1, 256>>>(t);
        if (t < TSTEPS - 1) {
            k_gather<<<192, 256>>>(embed);
            k_rnn<<<dim3(16, 8), 256>>>(W_ih, W_hh);
            k_rnnfin<<<64, 256>>>(bvec);
            k_logits<<<dim3(16, 16), 256>>>(W_out);
            k_stats_topk<<<16, 256>>>(nullptr, 0);
        }
    }
    k_final<<<1, 256>>>(out);
}

// round 2
// speedup vs baseline: 1.3284x; 1.3284x over previous
#include <cuda_runtime.h>
#include <math.h>
#include <stdint.h>

#define VOCAB 32000
#define HID   1024
#define BEAM  16
#define TSTEPS 16
#define KSPLIT 4
#define KCHUNK (HID / KSPLIT)   // 256

// ---------------- device scratch (static, allocation-free) ----------------
__device__ float g_zp[KSPLIT * BEAM * VOCAB]; // partial logits [ks][beam][col]
__device__ float g_tv[BEAM * BEAM];      // per-row top-16 values (logprob domain)
__device__ int   g_ti[BEAM * BEAM];      // per-row top-16 indices
__device__ int   g_seq[TSTEPS * BEAM];   // beam_seq [t][b]
__device__ float g_seqlp[TSTEPS * BEAM]; // beam_seq_lp [t][b]
__device__ float g_lps[BEAM];            // beam_lps
__device__ int   g_tok[BEAM];            // selected token per beam this step
__device__ int   g_perm[BEAM];           // selected source beam per beam
__device__ float g_x[2 * HID * BEAM];    // gathered [embed_row ; state_row] as [k][b]
__device__ float g_st[HID * BEAM];       // hidden state, col-major [k][b]
__device__ float g_acc[HID * BEAM];      // rnn partial accumulator [k][b]
__device__ unsigned long long g_h2[HID * 8]; // h packed beam-pairs [k][bp]

// ---------------- small helpers ----------------
__device__ __forceinline__ unsigned long long pack_key(float v, unsigned idx_inv) {
    unsigned u = __float_as_uint(v);
    u = (u & 0x80000000u) ? ~u : (u | 0x80000000u);
    return ((unsigned long long)u << 32) | (unsigned long long)idx_inv;
}
__device__ __forceinline__ float unpack_val(unsigned long long k) {
    unsigned u = (unsigned)(k >> 32);
    u = (u & 0x80000000u) ? (u ^ 0x80000000u) : ~u;
    return __uint_as_float(u);
}
__device__ __forceinline__ unsigned long long pack2f(float lo, float hi) {
    unsigned long long r;
    asm("mov.b64 %0, {%1, %2};" : "=l"(r) : "r"(__float_as_uint(lo)), "r"(__float_as_uint(hi)));
    return r;
}
__device__ __forceinline__ void unpack2(unsigned long long a, float& lo, float& hi) {
    unsigned ulo, uhi;
    asm("mov.b64 {%0, %1}, %2;" : "=r"(ulo), "=r"(uhi) : "l"(a));
    lo = __uint_as_float(ulo); hi = __uint_as_float(uhi);
}
__device__ __forceinline__ unsigned long long fma2(unsigned long long a, unsigned long long b,
                                                   unsigned long long c) {
    unsigned long long d;
    asm("fma.rn.f32x2 %0, %1, %2, %3;" : "=l"(d) : "l"(a), "l"(b), "l"(c));
    return d;
}

__device__ __forceinline__ unsigned long long blockMaxU64(unsigned long long v) {
    __shared__ unsigned long long red[8]; __shared__ unsigned long long out;
    #pragma unroll
    for (int o = 16; o; o >>= 1) {
        unsigned long long w = __shfl_down_sync(0xffffffffu, v, o);
        if (w > v) v = w;
    }
    if ((threadIdx.x & 31) == 0) red[threadIdx.x >> 5] = v;
    __syncthreads();
    if (threadIdx.x < 32) {
        unsigned long long w = (threadIdx.x < 8) ? red[threadIdx.x] : 0ull;
        #pragma unroll
        for (int o = 4; o; o >>= 1) {
            unsigned long long t = __shfl_down_sync(0xffffffffu, w, o);
            if (t > w) w = t;
        }
        if (threadIdx.x == 0) out = w;
    }
    __syncthreads();
    unsigned long long r = out; __syncthreads();
    return r;
}

// ---------------- kernels ----------------

__global__ void k_init(const float* __restrict__ state) {
    int i = blockIdx.x * 256 + threadIdx.x;
    if (i < HID * BEAM) {
        int k = i >> 4, b = i & 15;
        g_st[i] = state[b * HID + k];
    }
    if (i < TSTEPS * BEAM) { g_seq[i] = 0; g_seqlp[i] = 0.0f; }
    if (i < BEAM) g_lps[i] = 0.0f;
}

// Single fused pass per beam row: sum K-split partials, online max+sumexp,
// and exact top-16 of raw z (with -1000 on last vocab entry). Since
// log_softmax is a uniform shift, top-k on z == top-k on lp; values get
// -off applied at the end. jax top_k tie-breaking via packed keys.
__global__ void k_stats_topk(const float* __restrict__ ext, int use_ext) {
    int row = blockIdx.x, tid = threadIdx.x;
    const float* __restrict__ zp  = g_zp + (size_t)row * VOCAB;
    const float* __restrict__ src = ext + (size_t)row * VOCAB;

    __shared__ unsigned long long cand[16 * 256];
    #pragma unroll
    for (int j = 0; j < 16; j++) cand[j * 256 + tid] = 0ull;
    unsigned long long s15 = 0ull;

    float m = -INFINITY, s = 0.0f;
    for (int c = tid; c < VOCAB; c += 256) {
        float z;
        if (use_ext) z = src[c];
        else z = zp[c] + zp[c + 1 * BEAM * VOCAB]
                       + zp[c + 2 * BEAM * VOCAB]
                       + zp[c + 3 * BEAM * VOCAB];
        // online logsumexp
        if (z > m) { s = s * expf(m - z) + 1.0f; m = z; }
        else       { s += expf(z - m); }
        float v = (c == VOCAB - 1) ? z - 1000.0f : z;
        unsigned long long key = pack_key(v, 0xFFFFFFFFu - (unsigned)c);
        if (key > s15) {
            int j = 15;
            while (j > 0 && cand[(j - 1) * 256 + tid] < key) {
                cand[j * 256 + tid] = cand[(j - 1) * 256 + tid];
                j--;
            }
            cand[j * 256 + tid] = key;
            s15 = cand[15 * 256 + tid];
        }
    }
    // block reduce (m, s)
    __shared__ float rm[8], rs[8]; __shared__ float s_off;
    #pragma unroll
    for (int o = 16; o; o >>= 1) {
        float m2 = __shfl_down_sync(0xffffffffu, m, o);
        float s2 = __shfl_down_sync(0xffffffffu, s, o);
        if (m2 > m) { s = s * expf(m - m2) + s2; m = m2; }
        else        { s += s2 * expf(m2 - m); }
    }
    if ((tid & 31) == 0) { rm[tid >> 5] = m; rs[tid >> 5] = s; }
    __syncthreads();
    if (tid == 0) {
        float mm = rm[0], ss = rs[0];
        for (int w = 1; w < 8; w++) {
            float m2 = rm[w], s2 = rs[w];
            if (m2 > mm) { ss = ss * expf(mm - m2) + s2; mm = m2; }
            else         { ss += s2 * expf(m2 - mm); }
        }
        s_off = mm + logf(ss);
    }
    __syncthreads();
    float off = s_off;

    // 16 rounds of "max among keys strictly below previous winner"
    unsigned long long prev = ~0ull;
    int p = 0;
    for (int r = 0; r < 16; r++) {
        while (p < 16 && cand[p * 256 + tid] >= prev) p++;
        unsigned long long h = (p < 16) ? cand[p * 256 + tid] : 0ull;
        unsigned long long win = blockMaxU64(h);
        if (tid == 0) {
            unsigned lo = (unsigned)win;
            g_ti[row * 16 + r] = (int)(0xFFFFFFFFu - lo);
            g_tv[row * 16 + r] = unpack_val(win) - off;
        }
        prev = win;
    }
}

// second-level selection over 16x16 candidates; updates beam arrays
__global__ void k_select(int t) {
    int tid = threadIdx.x;
    int q = tid >> 4;
    float tvv = g_tv[tid];
    float cv = g_lps[q] + tvv;
    if (t == 0 && q != 0) cv = -INFINITY;
    unsigned long long key = pack_key(cv, 0xFFFFFFFFu - (unsigned)tid);

    __shared__ int   s_q[16], s_c[16];
    __shared__ float s_r[16], s_nl[16];

    unsigned long long prev = ~0ull;
    for (int r = 0; r < 16; r++) {
        unsigned long long h = (key < prev) ? key : 0ull;
        unsigned long long win = blockMaxU64(h);
        if (h == win && h != 0ull) {
            int c = g_ti[tid];
            s_q[r] = q; s_c[r] = c; s_r[r] = tvv;
            s_nl[r] = (c == 0 || t == TSTEPS - 1) ? -1000.0f : cv;
        }
        prev = win;
    }
    __syncthreads();

    __shared__ int   oseq[256];
    __shared__ float oslp[256];
    oseq[tid] = g_seq[tid];
    oslp[tid] = g_seqlp[tid];
    __syncthreads();

    int row = tid >> 4, j = tid & 15;
    if (row < t) {
        g_seq[tid]   = oseq[row * 16 + s_q[j]];
        g_seqlp[tid] = oslp[row * 16 + s_q[j]];
    } else if (row == t) {
        g_seq[tid]   = s_c[j];
        g_seqlp[tid] = s_r[j];
    }
    if (tid < 16) {
        g_lps[tid]  = s_nl[tid];
        g_tok[tid]  = s_c[tid];
        g_perm[tid] = s_q[tid];
    }
}

// gather x = [embed[tok[b]] ; st_old[perm[b]]] into [k][b] layout; zero g_acc
__global__ void k_gather(const float* __restrict__ embed) {
    int i = blockIdx.x * 256 + threadIdx.x;   // 192*256 = 49152
    if (i < 2 * HID * BEAM) {
        int k = i >> 4, b = i & 15;
        g_x[i] = (k < HID) ? embed[(size_t)g_tok[b] * HID + k]
                           : g_st[(k - HID) * 16 + g_perm[b]];
    } else {
        int j = i - 2 * HID * BEAM;
        if (j < HID * BEAM) g_acc[j] = 0.0f;
    }
}

// RNN partial GEMM: g_acc[col][b] += sum_k x[k][b] * W[k][col], K split by blockIdx.y
__global__ void k_rnn(const float* __restrict__ Wih, const float* __restrict__ Whh) {
    int tid = threadIdx.x;
    int col = blockIdx.x * 64 + (tid & 63);
    int bq  = tid >> 6;          // beam quad 0..3
    int ks  = blockIdx.y;        // 0..7, 256 k each (0-3: Wih, 4-7: Whh)
    const float* wp = (ks < 4) ? (Wih + (size_t)(ks * 256) * HID + col)
                               : (Whh + (size_t)(ks * 256 - HID) * HID + col);
    const float* xp = g_x + (size_t)(ks * 256) * 16 + bq * 4;
    unsigned long long a0 = 0ull, a1 = 0ull;
    #pragma unroll 4
    for (int kk = 0; kk < 256; kk++) {
        float w = __ldg(wp); wp += HID;
        unsigned long long ww = pack2f(w, w);
        ulonglong2 xv = *(const ulonglong2*)xp; xp += 16;
        a0 = fma2(xv.x, ww, a0);
        a1 = fma2(xv.y, ww, a1);
    }
    float f0, f1, f2, f3;
    unpack2(a0, f0, f1); unpack2(a1, f2, f3);
    float* dst = g_acc + col * 16 + bq * 4;
    atomicAdd(dst + 0, f0); atomicAdd(dst + 1, f1);
    atomicAdd(dst + 2, f2); atomicAdd(dst + 3, f3);
}

// finish RNN: tanh(acc + b) -> g_st, also pack beam-pair h2 for logits
__global__ void k_rnnfin(const float* __restrict__ bvec) {
    int j = blockIdx.x * 256 + threadIdx.x;   // 32*256 = 8192 = HID*8
    if (j < HID * 8) {
        int k = j >> 3, bp = j & 7;
        float bb = bvec[k];
        float t0 = tanhf(g_acc[k * 16 + bp * 2]     + bb);
        float t1 = tanhf(g_acc[k * 16 + bp * 2 + 1] + bb);
        g_st[k * 16 + bp * 2]     = t0;
        g_st[k * 16 + bp * 2 + 1] = t1;
        g_h2[k * 8 + bp] = pack2f(t0, t1);
    }
}

// logits: all 16 beams per W read. Each thread: 4 cols x 16 beams of
// accumulators (32 x f32x2). K-split by blockIdx.y into g_zp partials.
__global__ void __launch_bounds__(128) k_logits(const float* __restrict__ W) {
    __shared__ __align__(16) unsigned long long sh[KCHUNK * 8]; // 16KB
    int tid = threadIdx.x;
    int ks = blockIdx.y;
    int col = blockIdx.x * 512 + tid * 4;
    int colc = (col < VOCAB) ? col : 0;   // clamp; store guarded below

    // cooperative load of this K-chunk's packed h (beam pairs)
    for (int i = tid; i < KCHUNK * 8; i += 128)
        sh[i] = g_h2[ks * KCHUNK * 8 + i];
    __syncthreads();

    const float* wp = W + (size_t)(ks * KCHUNK) * VOCAB + colc;
    unsigned long long acc[8][4];
    #pragma unroll
    for (int bp = 0; bp < 8; bp++)
        #pragma unroll
        for (int c = 0; c < 4; c++) acc[bp][c] = 0ull;

    #pragma unroll 2
    for (int kk = 0; kk < KCHUNK; kk++) {
        float4 w = __ldg((const float4*)wp); wp += VOCAB;
        unsigned long long wq0 = pack2f(w.x, w.x);
        unsigned long long wq1 = pack2f(w.y, w.y);
        unsigned long long wq2 = pack2f(w.z, w.z);
        unsigned long long wq3 = pack2f(w.w, w.w);
        const ulonglong2* hrow = (const ulonglong2*)(sh + kk * 8);
        ulonglong2 h01 = hrow[0], h23 = hrow[1], h45 = hrow[2], h67 = hrow[3];
        unsigned long long hv[8] = {h01.x, h01.y, h23.x, h23.y,
                                    h45.x, h45.y, h67.x, h67.y};
        #pragma unroll
        for (int bp = 0; bp < 8; bp++) {
            acc[bp][0] = fma2(hv[bp], wq0, acc[bp][0]);
            acc[bp][1] = fma2(hv[bp], wq1, acc[bp][1]);
            acc[bp][2] = fma2(hv[bp], wq2, acc[bp][2]);
            acc[bp][3] = fma2(hv[bp], wq3, acc[bp][3]);
        }
    }

    if (col < VOCAB) {
        float* zbase = g_zp + (size_t)ks * BEAM * VOCAB + col;
        #pragma unroll
        for (int bp = 0; bp < 8; bp++) {
            float l0, h0, l1, h1, l2, h2v, l3, h3;
            unpack2(acc[bp][0], l0, h0); unpack2(acc[bp][1], l1, h1);
            unpack2(acc[bp][2], l2, h2v); unpack2(acc[bp][3], l3, h3);
            *(float4*)(zbase + (size_t)(2 * bp) * VOCAB)     = make_float4(l0, l1, l2, l3);
            *(float4*)(zbase + (size_t)(2 * bp + 1) * VOCAB) = make_float4(h0, h1, h2v, h3);
        }
    }
}

// write outputs: [beam_seq (256 as float) | beam_seq_lp (256) | beam_lps (16)]
__global__ void k_final(float* __restrict__ out) {
    int i = threadIdx.x;
    for (int j = i; j < 528; j += 256) {
        if (j < 256)      out[j] = (float)g_seq[j];
        else if (j < 512) out[j] = g_seqlp[j - 256];
        else              out[j] = g_lps[j - 512];
    }
}

// ---------------- launch ----------------
extern "C" void kernel_launch(void* const* d_in, const int* in_sizes, int n_in,
                              void* d_out, int out_size) {
    const float* state    = (const float*)d_in[0];
    const float* logprobs = (const float*)d_in[1];
    const float* embed    = (const float*)d_in[2];
    const float* W_ih     = (const float*)d_in[3];
    const float* W_hh     = (const float*)d_in[4];
    const float* bvec     = (const float*)d_in[5];
    const float* W_out    = (const float*)d_in[6];
    float* out = (float*)d_out;
    (void)in_sizes; (void)n_in; (void)out_size;

    k_init<<<64, 256>>>(state);
    k_stats_topk<<<16, 256>>>(logprobs, 1);
    for (int t = 0; t < TSTEPS; t++) {
        k_select<<<1, 256>>>(t);
        if (t < TSTEPS - 1) {
            k_gather<<<192, 256>>>(embed);
            k_rnn<<<dim3(16, 8), 256>>>(W_ih, W_hh);
            k_rnnfin<<<32, 256>>>(bvec);
            k_logits<<<dim3(63, KSPLIT), 128>>>(W_out);
            k_stats_topk<<<16, 256>>>(logprobs, 0);
        }
    }
    k_final<<<1, 256>>>(out);
}

// round 3
// speedup vs baseline: 1.6196x; 1.2192x over previous
#include <cuda_runtime.h>
#include <math.h>
#include <float.h>
#include <stdint.h>

#define VOCAB 32000
#define HID   1024
#define BEAM  16
#define TSTEPS 16
#define NLB 125   // logits blocks (125*256 == 32000)

// ---------------- device scratch ----------------
__device__ float g_tv[BEAM * BEAM];
__device__ int   g_ti[BEAM * BEAM];
__device__ int   g_seq[TSTEPS * BEAM];
__device__ float g_seqlp[TSTEPS * BEAM];
__device__ float g_lps[BEAM];
__device__ int   g_tok[BEAM];
__device__ int   g_perm[BEAM];
__device__ float g_st[HID * BEAM];                 // hidden state [k][b]
__device__ float g_racc[8 * HID * BEAM];           // rnn partials [ks][col][b]
__device__ unsigned long long g_h2[HID * 8];       // h packed beam-pairs [k][bp]
__device__ unsigned long long g_bkeys[NLB * BEAM * 16]; // per-block top16 keys
__device__ float2 g_bstat[NLB * BEAM];             // per-block (max, sumexp)

// ---------------- helpers ----------------
__device__ __forceinline__ unsigned long long pack_key(float v, unsigned idx_inv) {
    unsigned u = __float_as_uint(v);
    u = (u & 0x80000000u) ? ~u : (u | 0x80000000u);
    return ((unsigned long long)u << 32) | (unsigned long long)idx_inv;
}
__device__ __forceinline__ float unpack_val(unsigned long long k) {
    unsigned u = (unsigned)(k >> 32);
    u = (u & 0x80000000u) ? (u ^ 0x80000000u) : ~u;
    return __uint_as_float(u);
}
__device__ __forceinline__ unsigned long long pack2f(float lo, float hi) {
    unsigned long long r;
    asm("mov.b64 %0, {%1, %2};" : "=l"(r) : "r"(__float_as_uint(lo)), "r"(__float_as_uint(hi)));
    return r;
}
__device__ __forceinline__ void unpack2(unsigned long long a, float& lo, float& hi) {
    unsigned ulo, uhi;
    asm("mov.b64 {%0, %1}, %2;" : "=r"(ulo), "=r"(uhi) : "l"(a));
    lo = __uint_as_float(ulo); hi = __uint_as_float(uhi);
}
__device__ __forceinline__ unsigned long long fma2(unsigned long long a, unsigned long long b,
                                                   unsigned long long c) {
    unsigned long long d;
    asm("fma.rn.f32x2 %0, %1, %2, %3;" : "=l"(d) : "l"(a), "l"(b), "l"(c));
    return d;
}
__device__ __forceinline__ unsigned long long warpMaxU64(unsigned long long v) {
    #pragma unroll
    for (int o = 16; o; o >>= 1) {
        unsigned long long w = __shfl_xor_sync(0xffffffffu, v, o);
        if (w > v) v = w;
    }
    return v;
}
__device__ __forceinline__ unsigned long long blockMaxU64(unsigned long long v) {
    __shared__ unsigned long long red[8]; __shared__ unsigned long long out;
    v = warpMaxU64(v);
    if ((threadIdx.x & 31) == 0) red[threadIdx.x >> 5] = v;
    __syncthreads();
    if (threadIdx.x < 32) {
        unsigned long long w = (threadIdx.x < 8) ? red[threadIdx.x] : 0ull;
        #pragma unroll
        for (int o = 4; o; o >>= 1) {
            unsigned long long t = __shfl_down_sync(0xffffffffu, w, o);
            if (t > w) w = t;
        }
        if (threadIdx.x == 0) out = w;
    }
    __syncthreads();
    unsigned long long r = out; __syncthreads();
    return r;
}

// sorting-network compare-exchange, descending
#define CE(a, b) { unsigned long long _mx = (a) > (b) ? (a) : (b); \
                   unsigned long long _mn = (a) > (b) ? (b) : (a); (a) = _mx; (b) = _mn; }
#define SORT8(s0,s1,s2,s3,s4,s5,s6,s7) \
    CE(s0,s1) CE(s2,s3) CE(s4,s5) CE(s6,s7) \
    CE(s0,s2) CE(s1,s3) CE(s4,s6) CE(s5,s7) \
    CE(s1,s2) CE(s5,s6) CE(s0,s4) CE(s3,s7) \
    CE(s1,s5) CE(s2,s6) \
    CE(s1,s4) CE(s3,s6) \
    CE(s2,s4) CE(s3,s5) \
    CE(s3,s4)

// ---------------- kernels ----------------

__global__ void k_init(const float* __restrict__ state) {
    int i = blockIdx.x * 256 + threadIdx.x;
    if (i < HID * BEAM) {
        int k = i >> 4, b = i & 15;
        g_st[i] = state[b * HID + k];
    }
    if (i < TSTEPS * BEAM) { g_seq[i] = 0; g_seqlp[i] = 0.0f; }
    if (i < BEAM) g_lps[i] = 0.0f;
}

// Initial top-16 + logsumexp over EXTERNAL logprobs (runs once).
__global__ void k_stats_ext(const float* __restrict__ ext) {
    int row = blockIdx.x, tid = threadIdx.x;
    const float* __restrict__ src = ext + (size_t)row * VOCAB;

    __shared__ unsigned long long cand[16 * 256];
    #pragma unroll
    for (int j = 0; j < 16; j++) cand[j * 256 + tid] = 0ull;
    unsigned long long s15 = 0ull;

    float m = -FLT_MAX, s = 0.0f;
    for (int c = tid; c < VOCAB; c += 256) {
        float z = src[c];
        if (z > m) { s = s * expf(m - z) + 1.0f; m = z; }
        else       { s += expf(z - m); }
        float v = (c == VOCAB - 1) ? z - 1000.0f : z;
        unsigned long long key = pack_key(v, 0xFFFFFFFFu - (unsigned)c);
        if (key > s15) {
            int j = 15;
            while (j > 0 && cand[(j - 1) * 256 + tid] < key) {
                cand[j * 256 + tid] = cand[(j - 1) * 256 + tid];
                j--;
            }
            cand[j * 256 + tid] = key;
            s15 = cand[15 * 256 + tid];
        }
    }
    __shared__ float rm[8], rs[8]; __shared__ float s_off;
    #pragma unroll
    for (int o = 16; o; o >>= 1) {
        float m2 = __shfl_down_sync(0xffffffffu, m, o);
        float s2 = __shfl_down_sync(0xffffffffu, s, o);
        if (m2 > m) { s = s * expf(m - m2) + s2; m = m2; }
        else        { s += s2 * expf(m2 - m); }
    }
    if ((tid & 31) == 0) { rm[tid >> 5] = m; rs[tid >> 5] = s; }
    __syncthreads();
    if (tid == 0) {
        float mm = rm[0], ss = rs[0];
        for (int w = 1; w < 8; w++) {
            float m2 = rm[w], s2 = rs[w];
            if (m2 > mm) { ss = ss * expf(mm - m2) + s2; mm = m2; }
            else         { ss += s2 * expf(m2 - mm); }
        }
        s_off = mm + logf(ss);
    }
    __syncthreads();
    float off = s_off;

    unsigned long long prev = ~0ull;
    int p = 0;
    for (int r = 0; r < 16; r++) {
        while (p < 16 && cand[p * 256 + tid] >= prev) p++;
        unsigned long long h = (p < 16) ? cand[p * 256 + tid] : 0ull;
        unsigned long long win = blockMaxU64(h);
        if (tid == 0) {
            g_ti[row * 16 + r] = (int)(0xFFFFFFFFu - (unsigned)win);
            g_tv[row * 16 + r] = unpack_val(win) - off;
        }
        prev = win;
    }
}

// second-level selection over 16x16 candidates
__global__ void k_select(int t) {
    int tid = threadIdx.x;
    int q = tid >> 4;
    float tvv = g_tv[tid];
    float cv = g_lps[q] + tvv;
    if (t == 0 && q != 0) cv = -INFINITY;
    unsigned long long key = pack_key(cv, 0xFFFFFFFFu - (unsigned)tid);

    __shared__ int   s_q[16], s_c[16];
    __shared__ float s_r[16], s_nl[16];

    unsigned long long prev = ~0ull;
    for (int r = 0; r < 16; r++) {
        unsigned long long h = (key < prev) ? key : 0ull;
        unsigned long long win = blockMaxU64(h);
        if (h == win && h != 0ull) {
            int c = g_ti[tid];
            s_q[r] = q; s_c[r] = c; s_r[r] = tvv;
            s_nl[r] = (c == 0 || t == TSTEPS - 1) ? -1000.0f : cv;
        }
        prev = win;
    }
    __syncthreads();

    __shared__ int   oseq[256];
    __shared__ float oslp[256];
    oseq[tid] = g_seq[tid];
    oslp[tid] = g_seqlp[tid];
    __syncthreads();

    int row = tid >> 4, j = tid & 15;
    if (row < t) {
        g_seq[tid]   = oseq[row * 16 + s_q[j]];
        g_seqlp[tid] = oslp[row * 16 + s_q[j]];
    } else if (row == t) {
        g_seq[tid]   = s_c[j];
        g_seqlp[tid] = s_r[j];
    }
    if (tid < 16) {
        g_lps[tid]  = s_nl[tid];
        g_tok[tid]  = s_c[tid];
        g_perm[tid] = s_q[tid];
    }
}

// RNN partial GEMM with fused gather. grid(16, 8): x=col tile (64), y=ks chunk.
__global__ void __launch_bounds__(256) k_rnn(const float* __restrict__ embed,
                                             const float* __restrict__ Wih,
                                             const float* __restrict__ Whh) {
    __shared__ float sx[16 * 256];   // [b][k]
    int tid = threadIdx.x;
    int ks = blockIdx.y;
    if (ks < 4) {
        #pragma unroll
        for (int j = 0; j < 16; j++)
            sx[j * 256 + tid] = __ldg(&embed[(size_t)g_tok[j] * HID + ks * 256 + tid]);
    } else {
        #pragma unroll
        for (int j = 0; j < 16; j++)
            sx[j * 256 + tid] = g_st[((ks - 4) * 256 + tid) * 16 + g_perm[j]];
    }
    __syncthreads();

    int col = blockIdx.x * 64 + (tid & 63);
    int bq  = tid >> 6;
    const float* wp = ((ks < 4) ? (Wih + (size_t)(ks * 256) * HID)
                                : (Whh + (size_t)((ks - 4) * 256) * HID)) + col;
    const float* x0 = sx + bq * 4 * 256;
    unsigned long long a0 = 0ull, a1 = 0ull;
    #pragma unroll 4
    for (int k = 0; k < 256; k++) {
        float w = __ldg(wp); wp += HID;
        unsigned long long wq = pack2f(w, w);
        unsigned long long xa = pack2f(x0[k], x0[256 + k]);
        unsigned long long xb = pack2f(x0[512 + k], x0[768 + k]);
        a0 = fma2(xa, wq, a0);
        a1 = fma2(xb, wq, a1);
    }
    float f0, f1, f2, f3;
    unpack2(a0, f0, f1); unpack2(a1, f2, f3);
    *(float4*)&g_racc[((size_t)ks * HID + col) * 16 + bq * 4] = make_float4(f0, f1, f2, f3);
}

// sum partials + tanh -> g_st, pack h2
__global__ void k_rnnfin(const float* __restrict__ bvec) {
    int j = blockIdx.x * 256 + threadIdx.x;
    if (j >= HID * 8) return;
    int k = j >> 3, bp = j & 7;
    float a0 = 0.0f, a1 = 0.0f;
    #pragma unroll
    for (int ks = 0; ks < 8; ks++) {
        float2 v = *(const float2*)&g_racc[((size_t)ks * HID + k) * 16 + bp * 2];
        a0 += v.x; a1 += v.y;
    }
    float bb = bvec[k];
    float t0 = tanhf(a0 + bb), t1 = tanhf(a1 + bb);
    g_st[k * 16 + bp * 2]     = t0;
    g_st[k * 16 + bp * 2 + 1] = t1;
    g_h2[k * 8 + bp] = pack2f(t0, t1);
}

// logits GEMM + fused per-block stats & top-16. 125 blocks x 256 threads,
// 1 column x 16 beams per thread, full K so z never leaves registers.
__global__ void __launch_bounds__(256) k_logits(const float* __restrict__ W) {
    __shared__ __align__(16) unsigned long long sh[1024];       // h2 stage
    __shared__ __align__(16) unsigned long long skeys[16 * 256];
    __shared__ float sred[8 * 16];
    __shared__ float sbm[16];

    int tid = threadIdx.x;
    int lane = tid & 31, wid = tid >> 5;
    int col = blockIdx.x * 256 + tid;

    unsigned long long acc[8];
    #pragma unroll
    for (int i = 0; i < 8; i++) acc[i] = 0ull;
    const float* wp = W + col;

    for (int stage = 0; stage < 8; stage++) {
        #pragma unroll
        for (int i = 0; i < 4; i++) sh[i * 256 + tid] = g_h2[stage * 1024 + i * 256 + tid];
        __syncthreads();
        #pragma unroll 4
        for (int kk = 0; kk < 128; kk++) {
            float w = __ldg(wp); wp += VOCAB;
            unsigned long long wq = pack2f(w, w);
            const ulonglong2* hr = (const ulonglong2*)(sh + kk * 8);
            ulonglong2 h01 = hr[0], h23 = hr[1], h45 = hr[2], h67 = hr[3];
            acc[0] = fma2(h01.x, wq, acc[0]); acc[1] = fma2(h01.y, wq, acc[1]);
            acc[2] = fma2(h23.x, wq, acc[2]); acc[3] = fma2(h23.y, wq, acc[3]);
            acc[4] = fma2(h45.x, wq, acc[4]); acc[5] = fma2(h45.y, wq, acc[5]);
            acc[6] = fma2(h67.x, wq, acc[6]); acc[7] = fma2(h67.y, wq, acc[7]);
        }
        __syncthreads();
    }

    float z[16];
    #pragma unroll
    for (int i = 0; i < 8; i++) unpack2(acc[i], z[2 * i], z[2 * i + 1]);

    // ---- per-beam block max ----
    #pragma unroll
    for (int b = 0; b < 16; b++) {
        float v = z[b];
        #pragma unroll
        for (int o = 16; o; o >>= 1) v = fmaxf(v, __shfl_xor_sync(0xffffffffu, v, o));
        if (lane == 0) sred[wid * 16 + b] = v;
    }
    __syncthreads();
    if (tid < 16) {
        float m = sred[tid];
        #pragma unroll
        for (int w = 1; w < 8; w++) m = fmaxf(m, sred[w * 16 + tid]);
        sbm[tid] = m;
    }
    __syncthreads();
    // ---- per-beam block sum exp ----
    #pragma unroll
    for (int b = 0; b < 16; b++) {
        float e = expf(z[b] - sbm[b]);
        #pragma unroll
        for (int o = 16; o; o >>= 1) e += __shfl_xor_sync(0xffffffffu, e, o);
        if (lane == 0) sred[wid * 16 + b] = e;
    }
    __syncthreads();
    if (tid < 16) {
        float s = sred[tid];
        #pragma unroll
        for (int w = 1; w < 8; w++) s += sred[w * 16 + tid];
        g_bstat[blockIdx.x * 16 + tid] = make_float2(sbm[tid], s);
    }

    // ---- per-beam block top-16 ----
    #pragma unroll
    for (int b = 0; b < 16; b++) {
        float v = z[b];
        if (col == VOCAB - 1) v -= 1000.0f;
        skeys[b * 256 + tid] = pack_key(v, 0xFFFFFFFFu - (unsigned)col);
    }
    __syncthreads();

    #pragma unroll
    for (int bb = 0; bb < 2; bb++) {
        int b = wid * 2 + bb;
        const unsigned long long* kp = skeys + b * 256;
        unsigned long long s0 = kp[0 * 32 + lane], s1 = kp[1 * 32 + lane],
                           s2 = kp[2 * 32 + lane], s3 = kp[3 * 32 + lane],
                           s4 = kp[4 * 32 + lane], s5 = kp[5 * 32 + lane],
                           s6 = kp[6 * 32 + lane], s7 = kp[7 * 32 + lane];
        SORT8(s0, s1, s2, s3, s4, s5, s6, s7)
        #pragma unroll
        for (int r = 0; r < 16; r++) {
            unsigned long long win = warpMaxU64(s0);
            if (s0 == win) {
                s0 = s1; s1 = s2; s2 = s3; s3 = s4; s4 = s5; s5 = s6; s6 = s7; s7 = 0ull;
            }
            if (lane == r) g_bkeys[((size_t)blockIdx.x * 16 + b) * 16 + r] = win;
        }
    }
}

// combine 125 block partials per beam: logsumexp offset + exact top-16
__global__ void __launch_bounds__(256) k_reduce() {
    int beam = blockIdx.x, tid = threadIdx.x;
    __shared__ float rm[8], rs[8]; __shared__ float s_off;

    float m = -FLT_MAX, s = 0.0f;
    if (tid < NLB) {
        float2 st = g_bstat[tid * 16 + beam];
        m = st.x; s = st.y;
    }
    #pragma unroll
    for (int o = 16; o; o >>= 1) {
        float m2 = __shfl_xor_sync(0xffffffffu, m, o);
        float s2 = __shfl_xor_sync(0xffffffffu, s, o);
        float mm = fmaxf(m, m2);
        s = s * expf(m - mm) + s2 * expf(m2 - mm);
        m = mm;
    }
    if ((tid & 31) == 0) { rm[tid >> 5] = m; rs[tid >> 5] = s; }
    __syncthreads();
    if (tid == 0) {
        float mm = rm[0], ss = rs[0];
        for (int w = 1; w < 8; w++) {
            float m2 = rm[w], s2 = rs[w];
            float mx = fmaxf(mm, m2);
            ss = ss * expf(mm - mx) + s2 * expf(m2 - mx);
            mm = mx;
        }
        s_off = mm + logf(ss);
    }
    __syncthreads();
    float off = s_off;

    // top-16 of 2000 keys
    unsigned long long s0 = 0, s1 = 0, s2 = 0, s3 = 0, s4 = 0, s5 = 0, s6 = 0, s7 = 0;
    int base = tid * 8;
    if (base < NLB * 16) {
        int blk = base >> 4, r0 = base & 15;
        const unsigned long long* kp = g_bkeys + ((size_t)blk * 16 + beam) * 16 + r0;
        s0 = kp[0]; s1 = kp[1]; s2 = kp[2]; s3 = kp[3];
        s4 = kp[4]; s5 = kp[5]; s6 = kp[6]; s7 = kp[7];
    }
    SORT8(s0, s1, s2, s3, s4, s5, s6, s7)
    for (int r = 0; r < 16; r++) {
        unsigned long long win = blockMaxU64(s0);
        if (s0 == win && win != 0ull) {
            s0 = s1; s1 = s2; s2 = s3; s3 = s4; s4 = s5; s5 = s6; s6 = s7; s7 = 0ull;
        }
        if (tid == 0) {
            g_ti[beam * 16 + r] = (int)(0xFFFFFFFFu - (unsigned)win);
            g_tv[beam * 16 + r] = unpack_val(win) - off;
        }
    }
}

__global__ void k_final(float* __restrict__ out) {
    int i = threadIdx.x;
    for (int j = i; j < 528; j += 256) {
        if (j < 256)      out[j] = (float)g_seq[j];
        else if (j < 512) out[j] = g_seqlp[j - 256];
        else              out[j] = g_lps[j - 512];
    }
}

// ---------------- launch ----------------
extern "C" void kernel_launch(void* const* d_in, const int* in_sizes, int n_in,
                              void* d_out, int out_size) {
    const float* state    = (const float*)d_in[0];
    const float* logprobs = (const float*)d_in[1];
    const float* embed    = (const float*)d_in[2];
    const float* W_ih     = (const float*)d_in[3];
    const float* W_hh     = (const float*)d_in[4];
    const float* bvec     = (const float*)d_in[5];
    const float* W_out    = (const float*)d_in[6];
    float* out = (float*)d_out;
    (void)in_sizes; (void)n_in; (void)out_size;

    k_init<<<64, 256>>>(state);
    k_stats_ext<<<16, 256>>>(logprobs);
    for (int t = 0; t < TSTEPS; t++) {
        k_select<<<1, 256>>>(t);
        if (t < TSTEPS - 1) {
            k_rnn<<<dim3(16, 8), 256>>>(embed, W_ih, W_hh);
            k_rnnfin<<<32, 256>>>(bvec);
            k_logits<<<NLB, 256>>>(W_out);
            k_reduce<<<16, 256>>>();
        }
    }
    k_final<<<1, 256>>>(out);
}

// round 4
// speedup vs baseline: 2.2589x; 1.3948x over previous
#include <cuda_runtime.h>
#include <math.h>
#include <float.h>
#include <stdint.h>

#define VOCAB 32000
#define HID   1024
#define BEAM  16
#define TSTEPS 16
#define NLB 125   // logits blocks (125*256 == 32000)

// ---------------- device scratch ----------------
__device__ float g_tv[BEAM * BEAM];
__device__ int   g_ti[BEAM * BEAM];
__device__ int   g_seq[TSTEPS * BEAM];
__device__ float g_seqlp[TSTEPS * BEAM];
__device__ float g_lps[BEAM];
__device__ int   g_tok[BEAM];
__device__ int   g_perm[BEAM];
__device__ float g_st[HID * BEAM];                 // hidden state [k][b]
__device__ float g_racc[16 * HID * BEAM];          // rnn partials [ks][col][b]
__device__ unsigned long long g_h2[HID * 8];       // h packed beam-pairs [k][bp]
__device__ unsigned long long g_bkeys[NLB * BEAM * 16]; // per-block top16 keys
__device__ float2 g_bstat[NLB * BEAM];             // per-block (max, sumexp)

// ---------------- helpers ----------------
__device__ __forceinline__ unsigned long long pack_key(float v, unsigned idx_inv) {
    unsigned u = __float_as_uint(v);
    u = (u & 0x80000000u) ? ~u : (u | 0x80000000u);
    return ((unsigned long long)u << 32) | (unsigned long long)idx_inv;
}
__device__ __forceinline__ float unpack_val(unsigned long long k) {
    unsigned u = (unsigned)(k >> 32);
    u = (u & 0x80000000u) ? (u ^ 0x80000000u) : ~u;
    return __uint_as_float(u);
}
__device__ __forceinline__ unsigned long long pack2f(float lo, float hi) {
    unsigned long long r;
    asm("mov.b64 %0, {%1, %2};" : "=l"(r) : "r"(__float_as_uint(lo)), "r"(__float_as_uint(hi)));
    return r;
}
__device__ __forceinline__ void unpack2(unsigned long long a, float& lo, float& hi) {
    unsigned ulo, uhi;
    asm("mov.b64 {%0, %1}, %2;" : "=r"(ulo), "=r"(uhi) : "l"(a));
    lo = __uint_as_float(ulo); hi = __uint_as_float(uhi);
}
__device__ __forceinline__ unsigned long long fma2(unsigned long long a, unsigned long long b,
                                                   unsigned long long c) {
    unsigned long long d;
    asm("fma.rn.f32x2 %0, %1, %2, %3;" : "=l"(d) : "l"(a), "l"(b), "l"(c));
    return d;
}
__device__ __forceinline__ unsigned long long warpMaxU64(unsigned long long v) {
    #pragma unroll
    for (int o = 16; o; o >>= 1) {
        unsigned long long w = __shfl_xor_sync(0xffffffffu, v, o);
        if (w > v) v = w;
    }
    return v;
}
__device__ __forceinline__ unsigned long long blockMaxU64(unsigned long long v) {
    __shared__ unsigned long long red[8]; __shared__ unsigned long long out;
    v = warpMaxU64(v);
    if ((threadIdx.x & 31) == 0) red[threadIdx.x >> 5] = v;
    __syncthreads();
    if (threadIdx.x < 32) {
        unsigned long long w = (threadIdx.x < 8) ? red[threadIdx.x] : 0ull;
        #pragma unroll
        for (int o = 4; o; o >>= 1) {
            unsigned long long t = __shfl_down_sync(0xffffffffu, w, o);
            if (t > w) w = t;
        }
        if (threadIdx.x == 0) out = w;
    }
    __syncthreads();
    unsigned long long r = out; __syncthreads();
    return r;
}

#define CE(a, b) { unsigned long long _mx = (a) > (b) ? (a) : (b); \
                   unsigned long long _mn = (a) > (b) ? (b) : (a); (a) = _mx; (b) = _mn; }
#define SORT8(s0,s1,s2,s3,s4,s5,s6,s7) \
    CE(s0,s1) CE(s2,s3) CE(s4,s5) CE(s6,s7) \
    CE(s0,s2) CE(s1,s3) CE(s4,s6) CE(s5,s7) \
    CE(s1,s2) CE(s5,s6) CE(s0,s4) CE(s3,s7) \
    CE(s1,s5) CE(s2,s6) \
    CE(s1,s4) CE(s3,s6) \
    CE(s2,s4) CE(s3,s5) \
    CE(s3,s4)

// ---------------- kernels ----------------

__global__ void k_init(const float* __restrict__ state) {
    int i = blockIdx.x * 256 + threadIdx.x;
    if (i < HID * BEAM) {
        int k = i >> 4, b = i & 15;
        g_st[i] = state[b * HID + k];
    }
    if (i < TSTEPS * BEAM) { g_seq[i] = 0; g_seqlp[i] = 0.0f; }
    if (i < BEAM) g_lps[i] = 0.0f;
}

// Initial top-16 + logsumexp over EXTERNAL logprobs (runs once).
__global__ void k_stats_ext(const float* __restrict__ ext) {
    int row = blockIdx.x, tid = threadIdx.x;
    const float* __restrict__ src = ext + (size_t)row * VOCAB;

    __shared__ unsigned long long cand[16 * 256];
    #pragma unroll
    for (int j = 0; j < 16; j++) cand[j * 256 + tid] = 0ull;
    unsigned long long s15 = 0ull;

    float m = -FLT_MAX, s = 0.0f;
    for (int c = tid; c < VOCAB; c += 256) {
        float z = src[c];
        if (z > m) { s = s * expf(m - z) + 1.0f; m = z; }
        else       { s += expf(z - m); }
        float v = (c == VOCAB - 1) ? z - 1000.0f : z;
        unsigned long long key = pack_key(v, 0xFFFFFFFFu - (unsigned)c);
        if (key > s15) {
            int j = 15;
            while (j > 0 && cand[(j - 1) * 256 + tid] < key) {
                cand[j * 256 + tid] = cand[(j - 1) * 256 + tid];
                j--;
            }
            cand[j * 256 + tid] = key;
            s15 = cand[15 * 256 + tid];
        }
    }
    __shared__ float rm[8], rs[8]; __shared__ float s_off;
    #pragma unroll
    for (int o = 16; o; o >>= 1) {
        float m2 = __shfl_down_sync(0xffffffffu, m, o);
        float s2 = __shfl_down_sync(0xffffffffu, s, o);
        if (m2 > m) { s = s * expf(m - m2) + s2; m = m2; }
        else        { s += s2 * expf(m2 - m); }
    }
    if ((tid & 31) == 0) { rm[tid >> 5] = m; rs[tid >> 5] = s; }
    __syncthreads();
    if (tid == 0) {
        float mm = rm[0], ss = rs[0];
        for (int w = 1; w < 8; w++) {
            float m2 = rm[w], s2 = rs[w];
            if (m2 > mm) { ss = ss * expf(mm - m2) + s2; mm = m2; }
            else         { ss += s2 * expf(m2 - mm); }
        }
        s_off = mm + logf(ss);
    }
    __syncthreads();
    float off = s_off;

    unsigned long long prev = ~0ull;
    int p = 0;
    for (int r = 0; r < 16; r++) {
        while (p < 16 && cand[p * 256 + tid] >= prev) p++;
        unsigned long long h = (p < 16) ? cand[p * 256 + tid] : 0ull;
        unsigned long long win = blockMaxU64(h);
        if (tid == 0) {
            g_ti[row * 16 + r] = (int)(0xFFFFFFFFu - (unsigned)win);
            g_tv[row * 16 + r] = unpack_val(win) - off;
        }
        prev = win;
    }
}

// second-level selection over 16x16 candidates
__global__ void k_select(int t) {
    int tid = threadIdx.x;
    int q = tid >> 4;
    float tvv = g_tv[tid];
    float cv = g_lps[q] + tvv;
    if (t == 0 && q != 0) cv = -INFINITY;
    unsigned long long key = pack_key(cv, 0xFFFFFFFFu - (unsigned)tid);

    __shared__ int   s_q[16], s_c[16];
    __shared__ float s_r[16], s_nl[16];

    unsigned long long prev = ~0ull;
    for (int r = 0; r < 16; r++) {
        unsigned long long h = (key < prev) ? key : 0ull;
        unsigned long long win = blockMaxU64(h);
        if (h == win && h != 0ull) {
            int c = g_ti[tid];
            s_q[r] = q; s_c[r] = c; s_r[r] = tvv;
            s_nl[r] = (c == 0 || t == TSTEPS - 1) ? -1000.0f : cv;
        }
        prev = win;
    }
    __syncthreads();

    __shared__ int   oseq[256];
    __shared__ float oslp[256];
    oseq[tid] = g_seq[tid];
    oslp[tid] = g_seqlp[tid];
    __syncthreads();

    int row = tid >> 4, j = tid & 15;
    if (row < t) {
        g_seq[tid]   = oseq[row * 16 + s_q[j]];
        g_seqlp[tid] = oslp[row * 16 + s_q[j]];
    } else if (row == t) {
        g_seq[tid]   = s_c[j];
        g_seqlp[tid] = s_r[j];
    }
    if (tid < 16) {
        g_lps[tid]  = s_nl[tid];
        g_tok[tid]  = s_c[tid];
        g_perm[tid] = s_q[tid];
    }
}

// RNN partial GEMM with fused gather. grid(8, 16): x = 128-col tile, y = 128-k
// chunk of virtual K=2048 ([0,1024)=embed@W_ih, [1024,2048)=state@W_hh).
// Warp = one beam pair; lane = 4 cols (float4 W loads, prefetch 8 -> 4KB/warp).
__global__ void __launch_bounds__(256) k_rnn(const float* __restrict__ embed,
                                             const float* __restrict__ Wih,
                                             const float* __restrict__ Whh) {
    __shared__ unsigned long long sx2[8 * 128];   // [bp][k] packed beam pairs
    int tid = threadIdx.x;
    int ks = blockIdx.y;

    for (int e = tid; e < 1024; e += 256) {
        int bp = e >> 7, k = e & 127;
        float v0, v1;
        if (ks < 8) {
            int kk = ks * 128 + k;
            v0 = __ldg(&embed[(size_t)g_tok[2 * bp] * HID + kk]);
            v1 = __ldg(&embed[(size_t)g_tok[2 * bp + 1] * HID + kk]);
        } else {
            int kk = (ks - 8) * 128 + k;
            v0 = g_st[kk * 16 + g_perm[2 * bp]];
            v1 = g_st[kk * 16 + g_perm[2 * bp + 1]];
        }
        sx2[e] = pack2f(v0, v1);
    }
    __syncthreads();

    int lane = tid & 31, bp = tid >> 5;
    int col = blockIdx.x * 128 + lane * 4;
    const float* wbase = ((ks < 8) ? (Wih + (size_t)(ks * 128) * HID)
                                   : (Whh + (size_t)((ks - 8) * 128) * HID)) + col;
    unsigned long long a0 = 0, a1 = 0, a2 = 0, a3 = 0;
    const unsigned long long* xrow = sx2 + bp * 128;

    for (int k0 = 0; k0 < 128; k0 += 8) {
        float4 w[8];
        #pragma unroll
        for (int i = 0; i < 8; i++)
            w[i] = __ldg((const float4*)(wbase + (size_t)(k0 + i) * HID));
        #pragma unroll
        for (int i = 0; i < 8; i++) {
            unsigned long long h = xrow[k0 + i];
            a0 = fma2(h, pack2f(w[i].x, w[i].x), a0);
            a1 = fma2(h, pack2f(w[i].y, w[i].y), a1);
            a2 = fma2(h, pack2f(w[i].z, w[i].z), a2);
            a3 = fma2(h, pack2f(w[i].w, w[i].w), a3);
        }
    }
    float p0, q0, p1, q1, p2, q2, p3, q3;
    unpack2(a0, p0, q0); unpack2(a1, p1, q1);
    unpack2(a2, p2, q2); unpack2(a3, p3, q3);
    float* dst = g_racc + ((size_t)ks * HID + col) * 16 + bp * 2;
    *(float2*)(dst)      = make_float2(p0, q0);
    *(float2*)(dst + 16) = make_float2(p1, q1);
    *(float2*)(dst + 32) = make_float2(p2, q2);
    *(float2*)(dst + 48) = make_float2(p3, q3);
}

// sum 16 partials + tanh -> g_st, pack h2
__global__ void k_rnnfin(const float* __restrict__ bvec) {
    int j = blockIdx.x * 256 + threadIdx.x;
    if (j >= HID * 8) return;
    int k = j >> 3, bp = j & 7;
    float a0 = 0.0f, a1 = 0.0f;
    #pragma unroll
    for (int ks = 0; ks < 16; ks++) {
        float2 v = *(const float2*)&g_racc[((size_t)ks * HID + k) * 16 + bp * 2];
        a0 += v.x; a1 += v.y;
    }
    float bb = bvec[k];
    float t0 = tanhf(a0 + bb), t1 = tanhf(a1 + bb);
    g_st[k * 16 + bp * 2]     = t0;
    g_st[k * 16 + bp * 2 + 1] = t1;
    g_h2[k * 8 + bp] = pack2f(t0, t1);
}

// logits GEMM + fused per-block stats & top-16. 125 blocks x 256 threads,
// 1 column x 16 beams per thread, full K in registers. W loads prefetched in
// batches of 16 independent scalar LDGs (2KB/warp in flight).
__global__ void __launch_bounds__(256) k_logits(const float* __restrict__ W) {
    __shared__ __align__(16) unsigned long long sh[1024];       // h2 stage
    __shared__ __align__(16) unsigned long long skeys[16 * 256];
    __shared__ float sred[8 * 16];
    __shared__ float sbm[16];

    int tid = threadIdx.x;
    int lane = tid & 31, wid = tid >> 5;
    int col = blockIdx.x * 256 + tid;

    unsigned long long acc[8];
    #pragma unroll
    for (int i = 0; i < 8; i++) acc[i] = 0ull;
    const float* wp = W + col;

    for (int stage = 0; stage < 8; stage++) {
        #pragma unroll
        for (int i = 0; i < 4; i++) sh[i * 256 + tid] = g_h2[stage * 1024 + i * 256 + tid];
        __syncthreads();
        for (int kk = 0; kk < 128; kk += 16) {
            const float* p = wp + (size_t)kk * VOCAB;
            float w[16];
            #pragma unroll
            for (int i = 0; i < 16; i++) w[i] = __ldg(p + (size_t)i * VOCAB);
            #pragma unroll
            for (int i = 0; i < 16; i++) {
                unsigned long long wq = pack2f(w[i], w[i]);
                const ulonglong2* hr = (const ulonglong2*)(sh + (kk + i) * 8);
                ulonglong2 h01 = hr[0], h23 = hr[1], h45 = hr[2], h67 = hr[3];
                acc[0] = fma2(h01.x, wq, acc[0]); acc[1] = fma2(h01.y, wq, acc[1]);
                acc[2] = fma2(h23.x, wq, acc[2]); acc[3] = fma2(h23.y, wq, acc[3]);
                acc[4] = fma2(h45.x, wq, acc[4]); acc[5] = fma2(h45.y, wq, acc[5]);
                acc[6] = fma2(h67.x, wq, acc[6]); acc[7] = fma2(h67.y, wq, acc[7]);
            }
        }
        wp += (size_t)128 * VOCAB;
        __syncthreads();
    }

    float z[16];
    #pragma unroll
    for (int i = 0; i < 8; i++) unpack2(acc[i], z[2 * i], z[2 * i + 1]);

    // ---- per-beam block max ----
    #pragma unroll
    for (int b = 0; b < 16; b++) {
        float v = z[b];
        #pragma unroll
        for (int o = 16; o; o >>= 1) v = fmaxf(v, __shfl_xor_sync(0xffffffffu, v, o));
        if (lane == 0) sred[wid * 16 + b] = v;
    }
    __syncthreads();
    if (tid < 16) {
        float m = sred[tid];
        #pragma unroll
        for (int w = 1; w < 8; w++) m = fmaxf(m, sred[w * 16 + tid]);
        sbm[tid] = m;
    }
    __syncthreads();
    // ---- per-beam block sum exp ----
    #pragma unroll
    for (int b = 0; b < 16; b++) {
        float e = expf(z[b] - sbm[b]);
        #pragma unroll
        for (int o = 16; o; o >>= 1) e += __shfl_xor_sync(0xffffffffu, e, o);
        if (lane == 0) sred[wid * 16 + b] = e;
    }
    __syncthreads();
    if (tid < 16) {
        float s = sred[tid];
        #pragma unroll
        for (int w = 1; w < 8; w++) s += sred[w * 16 + tid];
        g_bstat[blockIdx.x * 16 + tid] = make_float2(sbm[tid], s);
    }

    // ---- per-beam block top-16 ----
    #pragma unroll
    for (int b = 0; b < 16; b++) {
        float v = z[b];
        if (col == VOCAB - 1) v -= 1000.0f;
        skeys[b * 256 + tid] = pack_key(v, 0xFFFFFFFFu - (unsigned)col);
    }
    __syncthreads();

    #pragma unroll
    for (int bb = 0; bb < 2; bb++) {
        int b = wid * 2 + bb;
        const unsigned long long* kp = skeys + b * 256;
        unsigned long long s0 = kp[0 * 32 + lane], s1 = kp[1 * 32 + lane],
                           s2 = kp[2 * 32 + lane], s3 = kp[3 * 32 + lane],
                           s4 = kp[4 * 32 + lane], s5 = kp[5 * 32 + lane],
                           s6 = kp[6 * 32 + lane], s7 = kp[7 * 32 + lane];
        SORT8(s0, s1, s2, s3, s4, s5, s6, s7)
        #pragma unroll
        for (int r = 0; r < 16; r++) {
            unsigned long long win = warpMaxU64(s0);
            if (s0 == win) {
                s0 = s1; s1 = s2; s2 = s3; s3 = s4; s4 = s5; s5 = s6; s6 = s7; s7 = 0ull;
            }
            if (lane == r) g_bkeys[((size_t)blockIdx.x * 16 + b) * 16 + r] = win;
        }
    }
}

// combine 125 block partials per beam: logsumexp offset + exact top-16
__global__ void __launch_bounds__(256) k_reduce() {
    int beam = blockIdx.x, tid = threadIdx.x;
    __shared__ float rm[8], rs[8]; __shared__ float s_off;

    float m = -FLT_MAX, s = 0.0f;
    if (tid < NLB) {
        float2 st = g_bstat[tid * 16 + beam];
        m = st.x; s = st.y;
    }
    #pragma unroll
    for (int o = 16; o; o >>= 1) {
        float m2 = __shfl_xor_sync(0xffffffffu, m, o);
        float s2 = __shfl_xor_sync(0xffffffffu, s, o);
        float mm = fmaxf(m, m2);
        s = s * expf(m - mm) + s2 * expf(m2 - mm);
        m = mm;
    }
    if ((tid & 31) == 0) { rm[tid >> 5] = m; rs[tid >> 5] = s; }
    __syncthreads();
    if (tid == 0) {
        float mm = rm[0], ss = rs[0];
        for (int w = 1; w < 8; w++) {
            float m2 = rm[w], s2 = rs[w];
            float mx = fmaxf(mm, m2);
            ss = ss * expf(mm - mx) + s2 * expf(m2 - mx);
            mm = mx;
        }
        s_off = mm + logf(ss);
    }
    __syncthreads();
    float off = s_off;

    unsigned long long s0 = 0, s1 = 0, s2 = 0, s3 = 0, s4 = 0, s5 = 0, s6 = 0, s7 = 0;
    int base = tid * 8;
    if (base < NLB * 16) {
        int blk = base >> 4, r0 = base & 15;
        const unsigned long long* kp = g_bkeys + ((size_t)blk * 16 + beam) * 16 + r0;
        s0 = kp[0]; s1 = kp[1]; s2 = kp[2]; s3 = kp[3];
        s4 = kp[4]; s5 = kp[5]; s6 = kp[6]; s7 = kp[7];
    }
    SORT8(s0, s1, s2, s3, s4, s5, s6, s7)
    for (int r = 0; r < 16; r++) {
        unsigned long long win = blockMaxU64(s0);
        if (s0 == win && win != 0ull) {
            s0 = s1; s1 = s2; s2 = s3; s3 = s4; s4 = s5; s5 = s6; s6 = s7; s7 = 0ull;
        }
        if (tid == 0) {
            g_ti[beam * 16 + r] = (int)(0xFFFFFFFFu - (unsigned)win);
            g_tv[beam * 16 + r] = unpack_val(win) - off;
        }
    }
}

__global__ void k_final(float* __restrict__ out) {
    int i = threadIdx.x;
    for (int j = i; j < 528; j += 256) {
        if (j < 256)      out[j] = (float)g_seq[j];
        else if (j < 512) out[j] = g_seqlp[j - 256];
        else              out[j] = g_lps[j - 512];
    }
}

// ---------------- launch ----------------
extern "C" void kernel_launch(void* const* d_in, const int* in_sizes, int n_in,
                              void* d_out, int out_size) {
    const float* state    = (const float*)d_in[0];
    const float* logprobs = (const float*)d_in[1];
    const float* embed    = (const float*)d_in[2];
    const float* W_ih     = (const float*)d_in[3];
    const float* W_hh     = (const float*)d_in[4];
    const float* bvec     = (const float*)d_in[5];
    const float* W_out    = (const float*)d_in[6];
    float* out = (float*)d_out;
    (void)in_sizes; (void)n_in; (void)out_size;

    k_init<<<64, 256>>>(state);
    k_stats_ext<<<16, 256>>>(logprobs);
    for (int t = 0; t < TSTEPS; t++) {
        k_select<<<1, 256>>>(t);
        if (t < TSTEPS - 1) {
            k_rnn<<<dim3(8, 16), 256>>>(embed, W_ih, W_hh);
            k_rnnfin<<<32, 256>>>(bvec);
            k_logits<<<NLB, 256>>>(W_out);
            k_reduce<<<16, 256>>>();
        }
    }
    k_final<<<1, 256>>>(out);
}

// round 5
// speedup vs baseline: 3.7055x; 1.6404x over previous
#include <cuda_runtime.h>
#include <math.h>
#include <float.h>
#include <stdint.h>

#define VOCAB 32000
#define HID   1024
#define BEAM  16
#define TSTEPS 16
#define NLB 125   // logits blocks (125*256 == 32000)

// ---------------- device scratch ----------------
__device__ float g_tv[BEAM * BEAM];
__device__ int   g_ti[BEAM * BEAM];
__device__ int   g_seq[TSTEPS * BEAM];
__device__ float g_seqlp[TSTEPS * BEAM];
__device__ float g_lps[BEAM];
__device__ int   g_tok[BEAM];
__device__ int   g_perm[BEAM];
__device__ float g_st[HID * BEAM];                 // hidden state [k][b]
__device__ float g_racc[16 * HID * BEAM];          // rnn partials [ks][col][b]
__device__ unsigned long long g_h2[HID * 8];       // h packed beam-pairs [k][bp]
__device__ unsigned long long g_bkeys[NLB * BEAM * 16]; // per-block top16 keys
__device__ float2 g_bstat[NLB * BEAM];             // per-block (max, sumexp)

// ---------------- helpers ----------------
__device__ __forceinline__ unsigned long long pack_key(float v, unsigned idx_inv) {
    unsigned u = __float_as_uint(v);
    u = (u & 0x80000000u) ? ~u : (u | 0x80000000u);
    return ((unsigned long long)u << 32) | (unsigned long long)idx_inv;
}
__device__ __forceinline__ float unpack_val(unsigned long long k) {
    unsigned u = (unsigned)(k >> 32);
    u = (u & 0x80000000u) ? (u ^ 0x80000000u) : ~u;
    return __uint_as_float(u);
}
__device__ __forceinline__ unsigned long long pack2f(float lo, float hi) {
    unsigned long long r;
    asm("mov.b64 %0, {%1, %2};" : "=l"(r) : "r"(__float_as_uint(lo)), "r"(__float_as_uint(hi)));
    return r;
}
__device__ __forceinline__ void unpack2(unsigned long long a, float& lo, float& hi) {
    unsigned ulo, uhi;
    asm("mov.b64 {%0, %1}, %2;" : "=r"(ulo), "=r"(uhi) : "l"(a));
    lo = __uint_as_float(ulo); hi = __uint_as_float(uhi);
}
__device__ __forceinline__ unsigned long long fma2(unsigned long long a, unsigned long long b,
                                                   unsigned long long c) {
    unsigned long long d;
    asm("fma.rn.f32x2 %0, %1, %2, %3;" : "=l"(d) : "l"(a), "l"(b), "l"(c));
    return d;
}
__device__ __forceinline__ unsigned long long warpMaxU64(unsigned long long v) {
    #pragma unroll
    for (int o = 16; o; o >>= 1) {
        unsigned long long w = __shfl_xor_sync(0xffffffffu, v, o);
        if (w > v) v = w;
    }
    return v;
}
__device__ __forceinline__ unsigned long long blockMaxU64(unsigned long long v) {
    __shared__ unsigned long long red[8]; __shared__ unsigned long long out;
    v = warpMaxU64(v);
    if ((threadIdx.x & 31) == 0) red[threadIdx.x >> 5] = v;
    __syncthreads();
    if (threadIdx.x < 32) {
        unsigned long long w = (threadIdx.x < 8) ? red[threadIdx.x] : 0ull;
        #pragma unroll
        for (int o = 4; o; o >>= 1) {
            unsigned long long t = __shfl_down_sync(0xffffffffu, w, o);
            if (t > w) w = t;
        }
        if (threadIdx.x == 0) out = w;
    }
    __syncthreads();
    unsigned long long r = out; __syncthreads();
    return r;
}

#define CE(a, b) { unsigned long long _mx = (a) > (b) ? (a) : (b); \
                   unsigned long long _mn = (a) > (b) ? (b) : (a); (a) = _mx; (b) = _mn; }
#define SORT8(s0,s1,s2,s3,s4,s5,s6,s7) \
    CE(s0,s1) CE(s2,s3) CE(s4,s5) CE(s6,s7) \
    CE(s0,s2) CE(s1,s3) CE(s4,s6) CE(s5,s7) \
    CE(s1,s2) CE(s5,s6) CE(s0,s4) CE(s3,s7) \
    CE(s1,s5) CE(s2,s6) \
    CE(s1,s4) CE(s3,s6) \
    CE(s2,s4) CE(s3,s5) \
    CE(s3,s4)

// ---------------- kernels ----------------

__global__ void k_init(const float* __restrict__ state) {
    int i = blockIdx.x * 256 + threadIdx.x;
    if (i < HID * BEAM) {
        int k = i >> 4, b = i & 15;
        g_st[i] = state[b * HID + k];
    }
    if (i < TSTEPS * BEAM) { g_seq[i] = 0; g_seqlp[i] = 0.0f; }
    if (i < BEAM) g_lps[i] = 0.0f;
}

// Initial top-16 + logsumexp over EXTERNAL logprobs (runs once).
__global__ void k_stats_ext(const float* __restrict__ ext) {
    int row = blockIdx.x, tid = threadIdx.x;
    const float* __restrict__ src = ext + (size_t)row * VOCAB;

    __shared__ unsigned long long cand[16 * 256];
    #pragma unroll
    for (int j = 0; j < 16; j++) cand[j * 256 + tid] = 0ull;
    unsigned long long s15 = 0ull;

    float m = -FLT_MAX, s = 0.0f;
    for (int c = tid; c < VOCAB; c += 256) {
        float z = src[c];
        if (z > m) { s = s * expf(m - z) + 1.0f; m = z; }
        else       { s += expf(z - m); }
        float v = (c == VOCAB - 1) ? z - 1000.0f : z;
        unsigned long long key = pack_key(v, 0xFFFFFFFFu - (unsigned)c);
        if (key > s15) {
            int j = 15;
            while (j > 0 && cand[(j - 1) * 256 + tid] < key) {
                cand[j * 256 + tid] = cand[(j - 1) * 256 + tid];
                j--;
            }
            cand[j * 256 + tid] = key;
            s15 = cand[15 * 256 + tid];
        }
    }
    __shared__ float rm[8], rs[8]; __shared__ float s_off;
    #pragma unroll
    for (int o = 16; o; o >>= 1) {
        float m2 = __shfl_down_sync(0xffffffffu, m, o);
        float s2 = __shfl_down_sync(0xffffffffu, s, o);
        if (m2 > m) { s = s * expf(m - m2) + s2; m = m2; }
        else        { s += s2 * expf(m2 - m); }
    }
    if ((tid & 31) == 0) { rm[tid >> 5] = m; rs[tid >> 5] = s; }
    __syncthreads();
    if (tid == 0) {
        float mm = rm[0], ss = rs[0];
        for (int w = 1; w < 8; w++) {
            float m2 = rm[w], s2 = rs[w];
            if (m2 > mm) { ss = ss * expf(mm - m2) + s2; mm = m2; }
            else         { ss += s2 * expf(m2 - mm); }
        }
        s_off = mm + logf(ss);
    }
    __syncthreads();
    float off = s_off;

    unsigned long long prev = ~0ull;
    int p = 0;
    for (int r = 0; r < 16; r++) {
        while (p < 16 && cand[p * 256 + tid] >= prev) p++;
        unsigned long long h = (p < 16) ? cand[p * 256 + tid] : 0ull;
        unsigned long long win = blockMaxU64(h);
        if (tid == 0) {
            g_ti[row * 16 + r] = (int)(0xFFFFFFFFu - (unsigned)win);
            g_tv[row * 16 + r] = unpack_val(win) - off;
        }
        prev = win;
    }
}

// second-level selection over 16x16 candidates
__global__ void k_select(int t) {
    int tid = threadIdx.x;
    int q = tid >> 4;
    float tvv = g_tv[tid];
    float cv = g_lps[q] + tvv;
    if (t == 0 && q != 0) cv = -INFINITY;
    unsigned long long key = pack_key(cv, 0xFFFFFFFFu - (unsigned)tid);

    __shared__ int   s_q[16], s_c[16];
    __shared__ float s_r[16], s_nl[16];

    unsigned long long prev = ~0ull;
    for (int r = 0; r < 16; r++) {
        unsigned long long h = (key < prev) ? key : 0ull;
        unsigned long long win = blockMaxU64(h);
        if (h == win && h != 0ull) {
            int c = g_ti[tid];
            s_q[r] = q; s_c[r] = c; s_r[r] = tvv;
            s_nl[r] = (c == 0 || t == TSTEPS - 1) ? -1000.0f : cv;
        }
        prev = win;
    }
    __syncthreads();

    __shared__ int   oseq[256];
    __shared__ float oslp[256];
    oseq[tid] = g_seq[tid];
    oslp[tid] = g_seqlp[tid];
    __syncthreads();

    int row = tid >> 4, j = tid & 15;
    if (row < t) {
        g_seq[tid]   = oseq[row * 16 + s_q[j]];
        g_seqlp[tid] = oslp[row * 16 + s_q[j]];
    } else if (row == t) {
        g_seq[tid]   = s_c[j];
        g_seqlp[tid] = s_r[j];
    }
    if (tid < 16) {
        g_lps[tid]  = s_nl[tid];
        g_tok[tid]  = s_c[tid];
        g_perm[tid] = s_q[tid];
    }
}

// RNN partial GEMM with fused gather. grid(8, 16): x = 128-col tile, y = 128-k
// chunk of virtual K=2048. Warp = beam pair; lane = 4 cols. Prefetch 16 rows of
// float4 W (64 regs) -- needs launch_bounds(,1) so ptxas doesn't clip regs.
__global__ void __launch_bounds__(256, 1) k_rnn(const float* __restrict__ embed,
                                                const float* __restrict__ Wih,
                                                const float* __restrict__ Whh) {
    __shared__ unsigned long long sx2[8 * 128];   // [bp][k] packed beam pairs
    int tid = threadIdx.x;
    int ks = blockIdx.y;

    for (int e = tid; e < 1024; e += 256) {
        int bp = e >> 7, k = e & 127;
        float v0, v1;
        if (ks < 8) {
            int kk = ks * 128 + k;
            v0 = __ldg(&embed[(size_t)g_tok[2 * bp] * HID + kk]);
            v1 = __ldg(&embed[(size_t)g_tok[2 * bp + 1] * HID + kk]);
        } else {
            int kk = (ks - 8) * 128 + k;
            v0 = g_st[kk * 16 + g_perm[2 * bp]];
            v1 = g_st[kk * 16 + g_perm[2 * bp + 1]];
        }
        sx2[e] = pack2f(v0, v1);
    }
    __syncthreads();

    int lane = tid & 31, bp = tid >> 5;
    int col = blockIdx.x * 128 + lane * 4;
    const float* wbase = ((ks < 8) ? (Wih + (size_t)(ks * 128) * HID)
                                   : (Whh + (size_t)((ks - 8) * 128) * HID)) + col;
    unsigned long long a0 = 0, a1 = 0, a2 = 0, a3 = 0;
    const unsigned long long* xrow = sx2 + bp * 128;

    for (int k0 = 0; k0 < 128; k0 += 16) {
        float4 w[16];
        #pragma unroll
        for (int i = 0; i < 16; i++)
            w[i] = __ldg((const float4*)(wbase + (size_t)(k0 + i) * HID));
        #pragma unroll
        for (int i = 0; i < 16; i++) {
            unsigned long long h = xrow[k0 + i];
            a0 = fma2(h, pack2f(w[i].x, w[i].x), a0);
            a1 = fma2(h, pack2f(w[i].y, w[i].y), a1);
            a2 = fma2(h, pack2f(w[i].z, w[i].z), a2);
            a3 = fma2(h, pack2f(w[i].w, w[i].w), a3);
        }
    }
    float p0, q0, p1, q1, p2, q2, p3, q3;
    unpack2(a0, p0, q0); unpack2(a1, p1, q1);
    unpack2(a2, p2, q2); unpack2(a3, p3, q3);
    float* dst = g_racc + ((size_t)ks * HID + col) * 16 + bp * 2;
    *(float2*)(dst)      = make_float2(p0, q0);
    *(float2*)(dst + 16) = make_float2(p1, q1);
    *(float2*)(dst + 32) = make_float2(p2, q2);
    *(float2*)(dst + 48) = make_float2(p3, q3);
}

// sum 16 partials + tanh -> g_st, pack h2
__global__ void k_rnnfin(const float* __restrict__ bvec) {
    int j = blockIdx.x * 256 + threadIdx.x;
    if (j >= HID * 8) return;
    int k = j >> 3, bp = j & 7;
    float a0 = 0.0f, a1 = 0.0f;
    #pragma unroll
    for (int ks = 0; ks < 16; ks++) {
        float2 v = *(const float2*)&g_racc[((size_t)ks * HID + k) * 16 + bp * 2];
        a0 += v.x; a1 += v.y;
    }
    float bb = bvec[k];
    float t0 = tanhf(a0 + bb), t1 = tanhf(a1 + bb);
    g_st[k * 16 + bp * 2]     = t0;
    g_st[k * 16 + bp * 2 + 1] = t1;
    g_h2[k * 8 + bp] = pack2f(t0, t1);
}

// logits GEMM + fused per-block stats & top-16. 125 blocks x 256 threads,
// 1 column x 16 beams per thread, full K in registers. W prefetched in batches
// of 32 independent scalar LDGs (4KB/warp in flight); launch_bounds(,1) to
// keep the batch live in registers.
__global__ void __launch_bounds__(256, 1) k_logits(const float* __restrict__ W) {
    __shared__ __align__(16) unsigned long long sh[1024];       // h2 stage
    __shared__ __align__(16) unsigned long long skeys[16 * 256];
    __shared__ float sred[8 * 16];
    __shared__ float sbm[16];

    int tid = threadIdx.x;
    int lane = tid & 31, wid = tid >> 5;
    int col = blockIdx.x * 256 + tid;

    unsigned long long acc[8];
    #pragma unroll
    for (int i = 0; i < 8; i++) acc[i] = 0ull;
    const float* wp = W + col;

    for (int stage = 0; stage < 8; stage++) {
        #pragma unroll
        for (int i = 0; i < 4; i++) sh[i * 256 + tid] = g_h2[stage * 1024 + i * 256 + tid];
        __syncthreads();
        for (int kk = 0; kk < 128; kk += 32) {
            const float* p = wp + (size_t)kk * VOCAB;
            float w[32];
            #pragma unroll
            for (int i = 0; i < 32; i++) w[i] = __ldg(p + (size_t)i * VOCAB);
            #pragma unroll
            for (int i = 0; i < 32; i++) {
                unsigned long long wq = pack2f(w[i], w[i]);
                const ulonglong2* hr = (const ulonglong2*)(sh + (kk + i) * 8);
                ulonglong2 h01 = hr[0], h23 = hr[1], h45 = hr[2], h67 = hr[3];
                acc[0] = fma2(h01.x, wq, acc[0]); acc[1] = fma2(h01.y, wq, acc[1]);
                acc[2] = fma2(h23.x, wq, acc[2]); acc[3] = fma2(h23.y, wq, acc[3]);
                acc[4] = fma2(h45.x, wq, acc[4]); acc[5] = fma2(h45.y, wq, acc[5]);
                acc[6] = fma2(h67.x, wq, acc[6]); acc[7] = fma2(h67.y, wq, acc[7]);
            }
        }
        wp += (size_t)128 * VOCAB;
        __syncthreads();
    }

    float z[16];
    #pragma unroll
    for (int i = 0; i < 8; i++) unpack2(acc[i], z[2 * i], z[2 * i + 1]);

    // ---- per-beam block max ----
    #pragma unroll
    for (int b = 0; b < 16; b++) {
        float v = z[b];
        #pragma unroll
        for (int o = 16; o; o >>= 1) v = fmaxf(v, __shfl_xor_sync(0xffffffffu, v, o));
        if (lane == 0) sred[wid * 16 + b] = v;
    }
    __syncthreads();
    if (tid < 16) {
        float m = sred[tid];
        #pragma unroll
        for (int w = 1; w < 8; w++) m = fmaxf(m, sred[w * 16 + tid]);
        sbm[tid] = m;
    }
    __syncthreads();
    // ---- per-beam block sum exp ----
    #pragma unroll
    for (int b = 0; b < 16; b++) {
        float e = expf(z[b] - sbm[b]);
        #pragma unroll
        for (int o = 16; o; o >>= 1) e += __shfl_xor_sync(0xffffffffu, e, o);
        if (lane == 0) sred[wid * 16 + b] = e;
    }
    __syncthreads();
    if (tid < 16) {
        float s = sred[tid];
        #pragma unroll
        for (int w = 1; w < 8; w++) s += sred[w * 16 + tid];
        g_bstat[blockIdx.x * 16 + tid] = make_float2(sbm[tid], s);
    }

    // ---- per-beam block top-16 ----
    #pragma unroll
    for (int b = 0; b < 16; b++) {
        float v = z[b];
        if (col == VOCAB - 1) v -= 1000.0f;
        skeys[b * 256 + tid] = pack_key(v, 0xFFFFFFFFu - (unsigned)col);
    }
    __syncthreads();

    #pragma unroll
    for (int bb = 0; bb < 2; bb++) {
        int b = wid * 2 + bb;
        const unsigned long long* kp = skeys + b * 256;
        unsigned long long s0 = kp[0 * 32 + lane], s1 = kp[1 * 32 + lane],
                           s2 = kp[2 * 32 + lane], s3 = kp[3 * 32 + lane],
                           s4 = kp[4 * 32 + lane], s5 = kp[5 * 32 + lane],
                           s6 = kp[6 * 32 + lane], s7 = kp[7 * 32 + lane];
        SORT8(s0, s1, s2, s3, s4, s5, s6, s7)
        #pragma unroll
        for (int r = 0; r < 16; r++) {
            unsigned long long win = warpMaxU64(s0);
            if (s0 == win) {
                s0 = s1; s1 = s2; s2 = s3; s3 = s4; s4 = s5; s5 = s6; s6 = s7; s7 = 0ull;
            }
            if (lane == r) g_bkeys[((size_t)blockIdx.x * 16 + b) * 16 + r] = win;
        }
    }
}

// combine 125 block partials per beam: logsumexp offset + exact top-16
__global__ void __launch_bounds__(256) k_reduce() {
    int beam = blockIdx.x, tid = threadIdx.x;
    __shared__ float rm[8], rs[8]; __shared__ float s_off;

    float m = -FLT_MAX, s = 0.0f;
    if (tid < NLB) {
        float2 st = g_bstat[tid * 16 + beam];
        m = st.x; s = st.y;
    }
    #pragma unroll
    for (int o = 16; o; o >>= 1) {
        float m2 = __shfl_xor_sync(0xffffffffu, m, o);
        float s2 = __shfl_xor_sync(0xffffffffu, s, o);
        float mm = fmaxf(m, m2);
        s = s * expf(m - mm) + s2 * expf(m2 - mm);
        m = mm;
    }
    if ((tid & 31) == 0) { rm[tid >> 5] = m; rs[tid >> 5] = s; }
    __syncthreads();
    if (tid == 0) {
        float mm = rm[0], ss = rs[0];
        for (int w = 1; w < 8; w++) {
            float m2 = rm[w], s2 = rs[w];
            float mx = fmaxf(mm, m2);
            ss = ss * expf(mm - mx) + s2 * expf(m2 - mx);
            mm = mx;
        }
        s_off = mm + logf(ss);
    }
    __syncthreads();
    float off = s_off;

    unsigned long long s0 = 0, s1 = 0, s2 = 0, s3 = 0, s4 = 0, s5 = 0, s6 = 0, s7 = 0;
    int base = tid * 8;
    if (base < NLB * 16) {
        int blk = base >> 4, r0 = base & 15;
        const unsigned long long* kp = g_bkeys + ((size_t)blk * 16 + beam) * 16 + r0;
        s0 = kp[0]; s1 = kp[1]; s2 = kp[2]; s3 = kp[3];
        s4 = kp[4]; s5 = kp[5]; s6 = kp[6]; s7 = kp[7];
    }
    SORT8(s0, s1, s2, s3, s4, s5, s6, s7)
    for (int r = 0; r < 16; r++) {
        unsigned long long win = blockMaxU64(s0);
        if (s0 == win && win != 0ull) {
            s0 = s1; s1 = s2; s2 = s3; s3 = s4; s4 = s5; s5 = s6; s6 = s7; s7 = 0ull;
        }
        if (tid == 0) {
            g_ti[beam * 16 + r] = (int)(0xFFFFFFFFu - (unsigned)win);
            g_tv[beam * 16 + r] = unpack_val(win) - off;
        }
    }
}

__global__ void k_final(float* __restrict__ out) {
    int i = threadIdx.x;
    for (int j = i; j < 528; j += 256) {
        if (j < 256)      out[j] = (float)g_seq[j];
        else if (j < 512) out[j] = g_seqlp[j - 256];
        else              out[j] = g_lps[j - 512];
    }
}

// ---------------- launch ----------------
extern "C" void kernel_launch(void* const* d_in, const int* in_sizes, int n_in,
                              void* d_out, int out_size) {
    const float* state    = (const float*)d_in[0];
    const float* logprobs = (const float*)d_in[1];
    const float* embed    = (const float*)d_in[2];
    const float* W_ih     = (const float*)d_in[3];
    const float* W_hh     = (const float*)d_in[4];
    const float* bvec     = (const float*)d_in[5];
    const float* W_out    = (const float*)d_in[6];
    float* out = (float*)d_out;
    (void)in_sizes; (void)n_in; (void)out_size;

    k_init<<<64, 256>>>(state);
    k_stats_ext<<<16, 256>>>(logprobs);
    for (int t = 0; t < TSTEPS; t++) {
        k_select<<<1, 256>>>(t);
        if (t < TSTEPS - 1) {
            k_rnn<<<dim3(8, 16), 256>>>(embed, W_ih, W_hh);
            k_rnnfin<<<32, 256>>>(bvec);
            k_logits<<<NLB, 256>>>(W_out);
            k_reduce<<<16, 256>>>();
        }
    }
    k_final<<<1, 256>>>(out);
}

// round 6
// speedup vs baseline: 4.1305x; 1.1147x over previous
#include <cuda_runtime.h>
#include <math.h>
#include <float.h>
#include <stdint.h>

#define VOCAB 32000
#define HID   1024
#define BEAM  16
#define TSTEPS 16
#define NLB 125   // logits blocks (125*256 == 32000)

// ---------------- device scratch ----------------
__device__ float g_tv[BEAM * BEAM];
__device__ int   g_ti[BEAM * BEAM];
__device__ int   g_seq[TSTEPS * BEAM];
__device__ float g_seqlp[TSTEPS * BEAM];
__device__ float g_lps[BEAM];
__device__ int   g_tok[BEAM];
__device__ int   g_perm[BEAM];
__device__ float g_st[HID * BEAM];                 // hidden state [k][b]
__device__ float g_racc[32 * HID * BEAM];          // rnn partials [p][col][b]
__device__ unsigned long long g_h2[HID * 8];       // h packed beam-pairs [k][bp]
__device__ unsigned long long g_bkeys[NLB * BEAM * 16]; // per-block top16 keys
__device__ float2 g_bstat[NLB * BEAM];             // per-block (max, sumexp)

// ---------------- helpers ----------------
__device__ __forceinline__ unsigned long long pack_key(float v, unsigned idx_inv) {
    unsigned u = __float_as_uint(v);
    u = (u & 0x80000000u) ? ~u : (u | 0x80000000u);
    return ((unsigned long long)u << 32) | (unsigned long long)idx_inv;
}
__device__ __forceinline__ float unpack_val(unsigned long long k) {
    unsigned u = (unsigned)(k >> 32);
    u = (u & 0x80000000u) ? (u ^ 0x80000000u) : ~u;
    return __uint_as_float(u);
}
__device__ __forceinline__ unsigned long long pack2f(float lo, float hi) {
    unsigned long long r;
    asm("mov.b64 %0, {%1, %2};" : "=l"(r) : "r"(__float_as_uint(lo)), "r"(__float_as_uint(hi)));
    return r;
}
__device__ __forceinline__ void unpack2(unsigned long long a, float& lo, float& hi) {
    unsigned ulo, uhi;
    asm("mov.b64 {%0, %1}, %2;" : "=r"(ulo), "=r"(uhi) : "l"(a));
    lo = __uint_as_float(ulo); hi = __uint_as_float(uhi);
}
__device__ __forceinline__ unsigned long long fma2(unsigned long long a, unsigned long long b,
                                                   unsigned long long c) {
    unsigned long long d;
    asm("fma.rn.f32x2 %0, %1, %2, %3;" : "=l"(d) : "l"(a), "l"(b), "l"(c));
    return d;
}
__device__ __forceinline__ void cp16(unsigned saddr, const void* gaddr) {
    asm volatile("cp.async.cg.shared.global [%0], [%1], 16;" :: "r"(saddr), "l"(gaddr));
}
__device__ __forceinline__ unsigned long long warpMaxU64(unsigned long long v) {
    #pragma unroll
    for (int o = 16; o; o >>= 1) {
        unsigned long long w = __shfl_xor_sync(0xffffffffu, v, o);
        if (w > v) v = w;
    }
    return v;
}
__device__ __forceinline__ unsigned long long blockMaxU64(unsigned long long v) {
    __shared__ unsigned long long red[8]; __shared__ unsigned long long out;
    v = warpMaxU64(v);
    if ((threadIdx.x & 31) == 0) red[threadIdx.x >> 5] = v;
    __syncthreads();
    if (threadIdx.x < 32) {
        unsigned long long w = (threadIdx.x < 8) ? red[threadIdx.x] : 0ull;
        #pragma unroll
        for (int o = 4; o; o >>= 1) {
            unsigned long long t = __shfl_down_sync(0xffffffffu, w, o);
            if (t > w) w = t;
        }
        if (threadIdx.x == 0) out = w;
    }
    __syncthreads();
    unsigned long long r = out; __syncthreads();
    return r;
}

#define CE(a, b) { unsigned long long _mx = (a) > (b) ? (a) : (b); \
                   unsigned long long _mn = (a) > (b) ? (b) : (a); (a) = _mx; (b) = _mn; }
#define SORT8(s0,s1,s2,s3,s4,s5,s6,s7) \
    CE(s0,s1) CE(s2,s3) CE(s4,s5) CE(s6,s7) \
    CE(s0,s2) CE(s1,s3) CE(s4,s6) CE(s5,s7) \
    CE(s1,s2) CE(s5,s6) CE(s0,s4) CE(s3,s7) \
    CE(s1,s5) CE(s2,s6) \
    CE(s1,s4) CE(s3,s6) \
    CE(s2,s4) CE(s3,s5) \
    CE(s3,s4)

// ---------------- kernels ----------------

__global__ void k_init(const float* __restrict__ state) {
    int i = blockIdx.x * 256 + threadIdx.x;
    if (i < HID * BEAM) {
        int k = i >> 4, b = i & 15;
        g_st[i] = state[b * HID + k];
    }
    if (i < TSTEPS * BEAM) { g_seq[i] = 0; g_seqlp[i] = 0.0f; }
    if (i < BEAM) g_lps[i] = 0.0f;
}

// Initial top-16 + logsumexp over EXTERNAL logprobs (runs once).
__global__ void k_stats_ext(const float* __restrict__ ext) {
    int row = blockIdx.x, tid = threadIdx.x;
    const float* __restrict__ src = ext + (size_t)row * VOCAB;

    __shared__ unsigned long long cand[16 * 256];
    #pragma unroll
    for (int j = 0; j < 16; j++) cand[j * 256 + tid] = 0ull;
    unsigned long long s15 = 0ull;

    float m = -FLT_MAX, s = 0.0f;
    for (int c = tid; c < VOCAB; c += 256) {
        float z = src[c];
        if (z > m) { s = s * expf(m - z) + 1.0f; m = z; }
        else       { s += expf(z - m); }
        float v = (c == VOCAB - 1) ? z - 1000.0f : z;
        unsigned long long key = pack_key(v, 0xFFFFFFFFu - (unsigned)c);
        if (key > s15) {
            int j = 15;
            while (j > 0 && cand[(j - 1) * 256 + tid] < key) {
                cand[j * 256 + tid] = cand[(j - 1) * 256 + tid];
                j--;
            }
            cand[j * 256 + tid] = key;
            s15 = cand[15 * 256 + tid];
        }
    }
    __shared__ float rm[8], rs[8]; __shared__ float s_off;
    #pragma unroll
    for (int o = 16; o; o >>= 1) {
        float m2 = __shfl_down_sync(0xffffffffu, m, o);
        float s2 = __shfl_down_sync(0xffffffffu, s, o);
        if (m2 > m) { s = s * expf(m - m2) + s2; m = m2; }
        else        { s += s2 * expf(m2 - m); }
    }
    if ((tid & 31) == 0) { rm[tid >> 5] = m; rs[tid >> 5] = s; }
    __syncthreads();
    if (tid == 0) {
        float mm = rm[0], ss = rs[0];
        for (int w = 1; w < 8; w++) {
            float m2 = rm[w], s2 = rs[w];
            if (m2 > mm) { ss = ss * expf(mm - m2) + s2; mm = m2; }
            else         { ss += s2 * expf(m2 - mm); }
        }
        s_off = mm + logf(ss);
    }
    __syncthreads();
    float off = s_off;

    unsigned long long prev = ~0ull;
    int p = 0;
    for (int r = 0; r < 16; r++) {
        while (p < 16 && cand[p * 256 + tid] >= prev) p++;
        unsigned long long h = (p < 16) ? cand[p * 256 + tid] : 0ull;
        unsigned long long win = blockMaxU64(h);
        if (tid == 0) {
            g_ti[row * 16 + r] = (int)(0xFFFFFFFFu - (unsigned)win);
            g_tv[row * 16 + r] = unpack_val(win) - off;
        }
        prev = win;
    }
}

// second-level selection over 16x16 candidates
__global__ void k_select(int t) {
    int tid = threadIdx.x;
    int q = tid >> 4;
    float tvv = g_tv[tid];
    float cv = g_lps[q] + tvv;
    if (t == 0 && q != 0) cv = -INFINITY;
    unsigned long long key = pack_key(cv, 0xFFFFFFFFu - (unsigned)tid);

    __shared__ int   s_q[16], s_c[16];
    __shared__ float s_r[16], s_nl[16];

    unsigned long long prev = ~0ull;
    for (int r = 0; r < 16; r++) {
        unsigned long long h = (key < prev) ? key : 0ull;
        unsigned long long win = blockMaxU64(h);
        if (h == win && h != 0ull) {
            int c = g_ti[tid];
            s_q[r] = q; s_c[r] = c; s_r[r] = tvv;
            s_nl[r] = (c == 0 || t == TSTEPS - 1) ? -1000.0f : cv;
        }
        prev = win;
    }
    __syncthreads();

    __shared__ int   oseq[256];
    __shared__ float oslp[256];
    oseq[tid] = g_seq[tid];
    oslp[tid] = g_seqlp[tid];
    __syncthreads();

    int row = tid >> 4, j = tid & 15;
    if (row < t) {
        g_seq[tid]   = oseq[row * 16 + s_q[j]];
        g_seqlp[tid] = oslp[row * 16 + s_q[j]];
    } else if (row == t) {
        g_seq[tid]   = s_c[j];
        g_seqlp[tid] = s_r[j];
    }
    if (tid < 16) {
        g_lps[tid]  = s_nl[tid];
        g_tok[tid]  = s_c[tid];
        g_perm[tid] = s_q[tid];
    }
}

// RNN partial GEMM, de-duplicated loads. grid(8, 16): x = 128-col tile,
// y = 128-k chunk of virtual K=2048. Thread = (col, khalf): unique coalesced
// W rows per warp; x beam-pairs broadcast from smem. 32 k-split partials.
__global__ void __launch_bounds__(256, 1) k_rnn(const float* __restrict__ embed,
                                                const float* __restrict__ Wih,
                                                const float* __restrict__ Whh) {
    __shared__ unsigned long long sx2[128 * 8];   // [k][bp] packed beam pairs
    int tid = threadIdx.x;
    int ks = blockIdx.y;

    for (int e = tid; e < 1024; e += 256) {
        int k = e >> 3, bp = e & 7;
        float v0, v1;
        if (ks < 8) {
            int kk = ks * 128 + k;
            v0 = __ldg(&embed[(size_t)g_tok[2 * bp] * HID + kk]);
            v1 = __ldg(&embed[(size_t)g_tok[2 * bp + 1] * HID + kk]);
        } else {
            int kk = (ks - 8) * 128 + k;
            v0 = g_st[kk * 16 + g_perm[2 * bp]];
            v1 = g_st[kk * 16 + g_perm[2 * bp + 1]];
        }
        sx2[e] = pack2f(v0, v1);
    }
    __syncthreads();

    int col = blockIdx.x * 128 + (tid & 127);
    int khalf = tid >> 7;                 // 0 or 1: 64 k each
    int baserow = (ks & 7) * 128 + khalf * 64;
    const float* Wsel = (ks < 8) ? Wih : Whh;
    const float* wp = Wsel + (size_t)baserow * HID + col;

    unsigned long long acc[8];
    #pragma unroll
    for (int i = 0; i < 8; i++) acc[i] = 0ull;

    for (int k0 = 0; k0 < 64; k0 += 16) {
        float w[16];
        #pragma unroll
        for (int i = 0; i < 16; i++)
            w[i] = __ldg(wp + (size_t)(k0 + i) * HID);
        #pragma unroll
        for (int i = 0; i < 16; i++) {
            unsigned long long wq = pack2f(w[i], w[i]);
            const ulonglong2* hr = (const ulonglong2*)(sx2 + (khalf * 64 + k0 + i) * 8);
            ulonglong2 h01 = hr[0], h23 = hr[1], h45 = hr[2], h67 = hr[3];
            acc[0] = fma2(h01.x, wq, acc[0]); acc[1] = fma2(h01.y, wq, acc[1]);
            acc[2] = fma2(h23.x, wq, acc[2]); acc[3] = fma2(h23.y, wq, acc[3]);
            acc[4] = fma2(h45.x, wq, acc[4]); acc[5] = fma2(h45.y, wq, acc[5]);
            acc[6] = fma2(h67.x, wq, acc[6]); acc[7] = fma2(h67.y, wq, acc[7]);
        }
    }
    unsigned long long* dst = (unsigned long long*)g_racc
                            + ((size_t)(ks * 2 + khalf) * HID + col) * 8;
    #pragma unroll
    for (int bp = 0; bp < 8; bp++) dst[bp] = acc[bp];
}

// sum 32 partials + tanh -> g_st, pack h2
__global__ void k_rnnfin(const float* __restrict__ bvec) {
    int j = blockIdx.x * 256 + threadIdx.x;
    if (j >= HID * 8) return;
    int k = j >> 3, bp = j & 7;
    float a0 = 0.0f, a1 = 0.0f;
    #pragma unroll 8
    for (int p = 0; p < 32; p++) {
        float2 v = *(const float2*)&g_racc[((size_t)p * HID + k) * 16 + bp * 2];
        a0 += v.x; a1 += v.y;
    }
    float bb = bvec[k];
    float t0 = tanhf(a0 + bb), t1 = tanhf(a1 + bb);
    g_st[k * 16 + bp * 2]     = t0;
    g_st[k * 16 + bp * 2 + 1] = t1;
    g_h2[k * 8 + bp] = pack2f(t0, t1);
}

// logits GEMM + fused per-block stats & top-16. 125 blocks x 256 threads,
// 1 column x 16 beams per thread. W staged through smem with cp.async double
// buffering (32 chunks of 32 k-rows); full h2 (64KB) resident in smem.
// Dynamic smem: [0,64K) h2, [64K,128K) two 32KB W buffers.
__global__ void __launch_bounds__(256, 1) k_logits(const float* __restrict__ W) {
    extern __shared__ __align__(16) unsigned long long dynsmem[];
    __shared__ float sred[8 * 16];
    __shared__ float sbm[16];

    int tid = threadIdx.x;
    int lane = tid & 31, wid = tid >> 5;
    int col = blockIdx.x * 256 + tid;

    unsigned sbase;
    asm("{ .reg .u64 t; cvta.to.shared.u64 t, %1; cvt.u32.u64 %0, t; }"
        : "=r"(sbase) : "l"(dynsmem));

    // prefetch W chunk 0 first so it overlaps the h2 preload
    {
        const float* gbase = W + (size_t)blockIdx.x * 256;
        unsigned sb = sbase + 65536;
        #pragma unroll
        for (int i = 0; i < 8; i++) {
            int lin = i * 256 + tid;
            int row = lin >> 6, cq = lin & 63;
            cp16(sb + (row << 10) + (cq << 4), gbase + (size_t)row * VOCAB + cq * 4);
        }
        asm volatile("cp.async.commit_group;");
    }
    // preload full h2 (1024 k x 8 bp)
    #pragma unroll
    for (int i = 0; i < 32; i++) dynsmem[i * 256 + tid] = g_h2[i * 256 + tid];

    unsigned long long acc[8];
    #pragma unroll
    for (int i = 0; i < 8; i++) acc[i] = 0ull;

    for (int c = 0; c < 32; c++) {
        __syncthreads();    // prev compute done; safe to overwrite other buffer
        if (c + 1 < 32) {
            const float* gbase = W + (size_t)((c + 1) * 32) * VOCAB + (size_t)blockIdx.x * 256;
            unsigned sb = sbase + 65536 + (((c + 1) & 1) << 15);
            #pragma unroll
            for (int i = 0; i < 8; i++) {
                int lin = i * 256 + tid;
                int row = lin >> 6, cq = lin & 63;
                cp16(sb + (row << 10) + (cq << 4), gbase + (size_t)row * VOCAB + cq * 4);
            }
            asm volatile("cp.async.commit_group;");
            asm volatile("cp.async.wait_group 1;");
        } else {
            asm volatile("cp.async.wait_group 0;");
        }
        __syncthreads();    // chunk c visible to all (incl. h2 on c==0)

        const float* wbuf = (const float*)((char*)dynsmem + 65536 + ((c & 1) << 15));
        const unsigned long long* hb = dynsmem + (size_t)c * 32 * 8;
        #pragma unroll
        for (int kk = 0; kk < 32; kk++) {
            float w = wbuf[kk * 256 + tid];
            unsigned long long wq = pack2f(w, w);
            const ulonglong2* hr = (const ulonglong2*)(hb + kk * 8);
            ulonglong2 h01 = hr[0], h23 = hr[1], h45 = hr[2], h67 = hr[3];
            acc[0] = fma2(h01.x, wq, acc[0]); acc[1] = fma2(h01.y, wq, acc[1]);
            acc[2] = fma2(h23.x, wq, acc[2]); acc[3] = fma2(h23.y, wq, acc[3]);
            acc[4] = fma2(h45.x, wq, acc[4]); acc[5] = fma2(h45.y, wq, acc[5]);
            acc[6] = fma2(h67.x, wq, acc[6]); acc[7] = fma2(h67.y, wq, acc[7]);
        }
    }

    float z[16];
    #pragma unroll
    for (int i = 0; i < 8; i++) unpack2(acc[i], z[2 * i], z[2 * i + 1]);

    // ---- per-beam block max ----
    #pragma unroll
    for (int b = 0; b < 16; b++) {
        float v = z[b];
        #pragma unroll
        for (int o = 16; o; o >>= 1) v = fmaxf(v, __shfl_xor_sync(0xffffffffu, v, o));
        if (lane == 0) sred[wid * 16 + b] = v;
    }
    __syncthreads();
    if (tid < 16) {
        float m = sred[tid];
        #pragma unroll
        for (int w = 1; w < 8; w++) m = fmaxf(m, sred[w * 16 + tid]);
        sbm[tid] = m;
    }
    __syncthreads();
    // ---- per-beam block sum exp ----
    #pragma unroll
    for (int b = 0; b < 16; b++) {
        float e = expf(z[b] - sbm[b]);
        #pragma unroll
        for (int o = 16; o; o >>= 1) e += __shfl_xor_sync(0xffffffffu, e, o);
        if (lane == 0) sred[wid * 16 + b] = e;
    }
    __syncthreads();
    if (tid < 16) {
        float s = sred[tid];
        #pragma unroll
        for (int w = 1; w < 8; w++) s += sred[w * 16 + tid];
        g_bstat[blockIdx.x * 16 + tid] = make_float2(sbm[tid], s);
    }

    // ---- per-beam block top-16 (reuse first W buffer as key space) ----
    unsigned long long* skeys = dynsmem + 8192;   // 32KB region (buffer 0)
    #pragma unroll
    for (int b = 0; b < 16; b++) {
        float v = z[b];
        if (col == VOCAB - 1) v -= 1000.0f;
        skeys[b * 256 + tid] = pack_key(v, 0xFFFFFFFFu - (unsigned)col);
    }
    __syncthreads();

    #pragma unroll
    for (int bb = 0; bb < 2; bb++) {
        int b = wid * 2 + bb;
        const unsigned long long* kp = skeys + b * 256;
        unsigned long long s0 = kp[0 * 32 + lane], s1 = kp[1 * 32 + lane],
                           s2 = kp[2 * 32 + lane], s3 = kp[3 * 32 + lane],
                           s4 = kp[4 * 32 + lane], s5 = kp[5 * 32 + lane],
                           s6 = kp[6 * 32 + lane], s7 = kp[7 * 32 + lane];
        SORT8(s0, s1, s2, s3, s4, s5, s6, s7)
        #pragma unroll
        for (int r = 0; r < 16; r++) {
            unsigned long long win = warpMaxU64(s0);
            if (s0 == win) {
                s0 = s1; s1 = s2; s2 = s3; s3 = s4; s4 = s5; s5 = s6; s6 = s7; s7 = 0ull;
            }
            if (lane == r) g_bkeys[((size_t)blockIdx.x * 16 + b) * 16 + r] = win;
        }
    }
}

// combine 125 block partials per beam: logsumexp offset + exact top-16
__global__ void __launch_bounds__(256) k_reduce() {
    int beam = blockIdx.x, tid = threadIdx.x;
    __shared__ float rm[8], rs[8]; __shared__ float s_off;

    float m = -FLT_MAX, s = 0.0f;
    if (tid < NLB) {
        float2 st = g_bstat[tid * 16 + beam];
        m = st.x; s = st.y;
    }
    #pragma unroll
    for (int o = 16; o; o >>= 1) {
        float m2 = __shfl_xor_sync(0xffffffffu, m, o);
        float s2 = __shfl_xor_sync(0xffffffffu, s, o);
        float mm = fmaxf(m, m2);
        s = s * expf(m - mm) + s2 * expf(m2 - mm);
        m = mm;
    }
    if ((tid & 31) == 0) { rm[tid >> 5] = m; rs[tid >> 5] = s; }
    __syncthreads();
    if (tid == 0) {
        float mm = rm[0], ss = rs[0];
        for (int w = 1; w < 8; w++) {
            float m2 = rm[w], s2 = rs[w];
            float mx = fmaxf(mm, m2);
            ss = ss * expf(mm - mx) + s2 * expf(m2 - mx);
            mm = mx;
        }
        s_off = mm + logf(ss);
    }
    __syncthreads();
    float off = s_off;

    unsigned long long s0 = 0, s1 = 0, s2 = 0, s3 = 0, s4 = 0, s5 = 0, s6 = 0, s7 = 0;
    int base = tid * 8;
    if (base < NLB * 16) {
        int blk = base >> 4, r0 = base & 15;
        const unsigned long long* kp = g_bkeys + ((size_t)blk * 16 + beam) * 16 + r0;
        s0 = kp[0]; s1 = kp[1]; s2 = kp[2]; s3 = kp[3];
        s4 = kp[4]; s5 = kp[5]; s6 = kp[6]; s7 = kp[7];
    }
    SORT8(s0, s1, s2, s3, s4, s5, s6, s7)
    for (int r = 0; r < 16; r++) {
        unsigned long long win = blockMaxU64(s0);
        if (s0 == win && win != 0ull) {
            s0 = s1; s1 = s2; s2 = s3; s3 = s4; s4 = s5; s5 = s6; s6 = s7; s7 = 0ull;
        }
        if (tid == 0) {
            g_ti[beam * 16 + r] = (int)(0xFFFFFFFFu - (unsigned)win);
            g_tv[beam * 16 + r] = unpack_val(win) - off;
        }
    }
}

__global__ void k_final(float* __restrict__ out) {
    int i = threadIdx.x;
    for (int j = i; j < 528; j += 256) {
        if (j < 256)      out[j] = (float)g_seq[j];
        else if (j < 512) out[j] = g_seqlp[j - 256];
        else              out[j] = g_lps[j - 512];
    }
}

// ---------------- launch ----------------
extern "C" void kernel_launch(void* const* d_in, const int* in_sizes, int n_in,
                              void* d_out, int out_size) {
    const float* state    = (const float*)d_in[0];
    const float* logprobs = (const float*)d_in[1];
    const float* embed    = (const float*)d_in[2];
    const float* W_ih     = (const float*)d_in[3];
    const float* W_hh     = (const float*)d_in[4];
    const float* bvec     = (const float*)d_in[5];
    const float* W_out    = (const float*)d_in[6];
    float* out = (float*)d_out;
    (void)in_sizes; (void)n_in; (void)out_size;

    const int LOGITS_SMEM = 128 * 1024;   // 64KB h2 + 2x32KB W buffers
    cudaFuncSetAttribute(k_logits, cudaFuncAttributeMaxDynamicSharedMemorySize,
                         LOGITS_SMEM);

    k_init<<<64, 256>>>(state);
    k_stats_ext<<<16, 256>>>(logprobs);
    for (int t = 0; t < TSTEPS; t++) {
        k_select<<<1, 256>>>(t);
        if (t < TSTEPS - 1) {
            k_rnn<<<dim3(8, 16), 256>>>(embed, W_ih, W_hh);
            k_rnnfin<<<32, 256>>>(bvec);
            k_logits<<<NLB, 256, LOGITS_SMEM>>>(W_out);
            k_reduce<<<16, 256>>>();
        }
    }
    k_final<<<1, 256>>>(out);
}